// round 5
// baseline (speedup 1.0000x reference)
#include <cuda_runtime.h>
#include <cstdint>

#define NEG_INF_F (-1e9f)
#define HTHRESH_F (-1e8f)

// B=8, S=512, D=1024, H=16, DK=64
#define BB 8
#define SS 512
#define DD 1024
#define HH 16
#define DK 64
#define MTOT (BB*SS)          // 4096
#define BHTOT (BB*HH)         // 128

// -------- scratch (device globals; no cudaMalloc allowed) --------
__device__ float g_q[BB*HH*SS*DK];
__device__ float g_k[BB*HH*SS*DK];
__device__ float g_v[BB*HH*SS*DK];
__device__ float g_ctx[MTOT*DD];
__device__ float g_res[MTOT*DD];

// -------- helpers --------
__device__ __forceinline__ unsigned f2tf(float f) {
    unsigned u;
    asm("cvt.rna.tf32.f32 %0, %1;" : "=r"(u) : "f"(f));
    return u;
}
__device__ __forceinline__ float tf2f(float f) {
    return __uint_as_float(f2tf(f));
}
__device__ __forceinline__ void mma8(float c[4], const unsigned a[4], unsigned b0, unsigned b1) {
    asm volatile(
        "mma.sync.aligned.m16n8k8.row.col.f32.tf32.tf32.f32 "
        "{%0,%1,%2,%3}, {%4,%5,%6,%7}, {%8,%9}, {%0,%1,%2,%3};\n"
        : "+f"(c[0]), "+f"(c[1]), "+f"(c[2]), "+f"(c[3])
        : "r"(a[0]), "r"(a[1]), "r"(a[2]), "r"(a[3]), "r"(b0), "r"(b1));
}
__device__ __forceinline__ void cp16(float* smem_dst, const float* gsrc) {
    unsigned d = (unsigned)__cvta_generic_to_shared(smem_dst);
    asm volatile("cp.async.cg.shared.global [%0], [%1], 16;\n" :: "r"(d), "l"(gsrc));
}
__device__ __forceinline__ void cp_commit() {
    asm volatile("cp.async.commit_group;\n");
}
template<int N>
__device__ __forceinline__ void cp_wait() {
    asm volatile("cp.async.wait_group %0;\n" :: "n"(N));
}

// =====================================================================
// GEMM: C[4096,1024] = A @ W (+bias [+residual])
// 128x128x32 tiles, 3-stage cp.async pipeline, XOR-swizzled smem.
// 256 threads = 8 warps in 2(M) x 4(N); warp tile 64x32.
// RNA tf32 rounding applied at fragment load (matches R3 numerics).
// __launch_bounds__(256,2) forces 2 CTAs/SM.
// MODE 0: QKV (z selects W/bias/dst, scatter to [B,H,S,DK])
// MODE 1: out-proj + bias + residual -> g_res
// =====================================================================
#define GBM 128
#define GBN 128
#define GBK 32
#define GST 3
#define GEMM_SMEM_BYTES (GST * (GBM*GBK + GBK*GBN) * 4)   // 98304

template<int MODE>
__global__ __launch_bounds__(256, 2)
void gemm_tf32_kernel(const float* __restrict__ Aparam,
                      const float* __restrict__ W0, const float* __restrict__ W1,
                      const float* __restrict__ W2,
                      const float* __restrict__ bias0, const float* __restrict__ bias1,
                      const float* __restrict__ bias2,
                      const float* __restrict__ xres)
{
    extern __shared__ float gsm[];
    float* sA = gsm;                       // [GST][128*32]
    float* sB = gsm + GST * (GBM * GBK);   // [GST][32*128]

    const int z = blockIdx.z;
    const float* W    = (z == 0) ? W0 : (z == 1 ? W1 : W2);
    const float* bias = (z == 0) ? bias0 : (z == 1 ? bias1 : bias2);
    const float* A    = (MODE == 0) ? Aparam : g_ctx;
    float* dst;
    if (MODE == 0) dst = (z == 0) ? g_q : (z == 1 ? g_k : g_v);
    else           dst = g_res;

    const int m0 = blockIdx.x * GBM;
    const int n0 = blockIdx.y * GBN;
    const int tid = threadIdx.x;
    const int warp = tid >> 5, lane = tid & 31, gid = lane >> 2, tig = lane & 3;
    const int wm = warp & 1, wn = warp >> 1;    // 2 x 4 warp grid; warp tile 64x32

    float acc[4][4][4];
    #pragma unroll
    for (int i = 0; i < 4; i++)
        #pragma unroll
        for (int j = 0; j < 4; j++)
            #pragma unroll
            for (int k = 0; k < 4; k++) acc[i][j][k] = 0.f;

    // ---- tile loader (cp.async, swizzled) ----
    auto load_tile = [&](int st, int kt) {
        float* dA = sA + st * (GBM * GBK);
        float* dB = sB + st * (GBK * GBN);
        #pragma unroll
        for (int j = 0; j < 4; j++) {            // A: 128 rows x 8 chunks
            int idx = tid + 256 * j;
            int r = idx >> 3, c = idx & 7;
            cp16(dA + r * 32 + ((c ^ (r & 7)) << 2),
                 A + (size_t)(m0 + r) * DD + kt + (c << 2));
        }
        #pragma unroll
        for (int j = 0; j < 4; j++) {            // B: 32 rows x 32 chunks
            int idx = tid + 256 * j;
            int r = idx >> 5, c = idx & 31;
            cp16(dB + r * 128 + ((c ^ (r & 7)) << 2),
                 W + (size_t)(kt + r) * DD + n0 + (c << 2));
        }
    };

    // prologue: stages 0..GST-2
    #pragma unroll
    for (int s = 0; s < GST - 1; s++) { load_tile(s, s * GBK); cp_commit(); }

    const int NIT = DD / GBK;   // 32
    for (int it = 0; it < NIT; it++) {
        cp_wait<GST - 2>();
        __syncthreads();
        int nxt = it + GST - 1;
        if (nxt < NIT) load_tile(nxt % GST, nxt * GBK);
        cp_commit();

        const float* tA = sA + (it % GST) * (GBM * GBK);
        const float* tB = sB + (it % GST) * (GBK * GBN);
        #pragma unroll
        for (int kk = 0; kk < GBK; kk += 8) {
            unsigned a[4][4];
            const int c0 = kk >> 2;
            #pragma unroll
            for (int mf = 0; mf < 4; mf++) {
                int R = wm * 64 + mf * 16 + gid;     // R&7 == gid
                a[mf][0] = f2tf(tA[R * 32 + ((c0 ^ gid) << 2) + tig]);
                a[mf][1] = f2tf(tA[(R + 8) * 32 + ((c0 ^ gid) << 2) + tig]);
                a[mf][2] = f2tf(tA[R * 32 + (((c0 + 1) ^ gid) << 2) + tig]);
                a[mf][3] = f2tf(tA[(R + 8) * 32 + (((c0 + 1) ^ gid) << 2) + tig]);
            }
            #pragma unroll
            for (int nf = 0; nf < 4; nf++) {
                int nb = wn * 32 + nf * 8 + gid;
                int cc = nb >> 2, el = nb & 3;
                int k0 = kk + tig, k1 = kk + 4 + tig;
                unsigned b0 = f2tf(tB[k0 * 128 + ((cc ^ (k0 & 7)) << 2) + el]);
                unsigned b1 = f2tf(tB[k1 * 128 + ((cc ^ (k1 & 7)) << 2) + el]);
                #pragma unroll
                for (int mf = 0; mf < 4; mf++) mma8(acc[mf][nf], a[mf], b0, b1);
            }
        }
    }

    // epilogue
    #pragma unroll
    for (int mf = 0; mf < 4; mf++) {
        #pragma unroll
        for (int rr = 0; rr < 2; rr++) {
            int m = m0 + wm * 64 + mf * 16 + gid + rr * 8;
            #pragma unroll
            for (int nf = 0; nf < 4; nf++) {
                int n = n0 + wn * 32 + nf * 8 + tig * 2;
                float v0 = acc[mf][nf][rr * 2 + 0] + bias[n];
                float v1 = acc[mf][nf][rr * 2 + 1] + bias[n + 1];
                if (MODE == 0) {
                    int bidx = m >> 9, s = m & 511, hh = n >> 6, d = n & 63;
                    *reinterpret_cast<float2*>(
                        &dst[(((size_t)bidx * HH + hh) * SS + s) * DK + d]) = make_float2(v0, v1);
                } else {
                    v0 += xres[(size_t)m * DD + n];
                    v1 += xres[(size_t)m * DD + n + 1];
                    *reinterpret_cast<float2*>(&dst[(size_t)m * DD + n]) = make_float2(v0, v1);
                }
            }
        }
    }
}

// =====================================================================
// Fused attention kernel: block = (b,h, 64-row q-tile), 256 threads.
//   phase1: S = Q @ K^T * 0.125 (RNA tf32 at frag load)
//   phase2: row softmax; attn to gmem; P (tf32-rounded) stays in smem
//   phase3: ctx = P @ V, V triple-buffered, RNA tf32 on V frags
// =====================================================================
#define AST 72
#define SK_FLOATS (512 * AST)        // 36864
#define VB_FLOATS (64 * AST)         // 4608
#define ATTN_SMEM_BYTES ((SK_FLOATS + 3 * VB_FLOATS) * 4)   // 202752

__global__ __launch_bounds__(256)
void attn_fused_kernel(const float* __restrict__ help_vals,
                       const int* __restrict__ help_mask,
                       const int* __restrict__ amask,
                       float* __restrict__ attn_out)
{
    extern __shared__ float smem[];
    float* sK = smem;                               // K tile / scores (stride 516)
    float* vb0 = smem + SK_FLOATS;                  // Q, then V chunks
    float* vb1 = vb0 + VB_FLOATS;
    float* vb2 = vb1 + VB_FLOATS;

    const int bh = blockIdx.x;
    const int b = bh >> 4;
    const int h = bh & 15;
    const int q0 = blockIdx.y * 64;
    const int tid = threadIdx.x;
    const int warp = tid >> 5, lane = tid & 31, gid = lane >> 2, tig = lane & 3;

    const float* vsrcb = g_v + (size_t)bh * SS * DK;

    // ---- async load Q tile (into vb0) and full K ----
    {
        const float* qsrc = g_q + ((size_t)bh * SS + q0) * DK;
        #pragma unroll
        for (int j = 0; j < 4; j++) {
            int idx = tid + 256 * j;
            int r = idx >> 4, c = (idx & 15) << 2;
            cp16(vb0 + r * AST + c, qsrc + r * DK + c);
        }
        const float* ksrc = g_k + (size_t)bh * SS * DK;
        #pragma unroll
        for (int j = 0; j < 32; j++) {
            int idx = tid + 256 * j;
            int r = idx >> 4, c = (idx & 15) << 2;
            cp16(sK + r * AST + c, ksrc + r * DK + c);
        }
        cp_commit();
        cp_wait<0>();
        __syncthreads();
    }

    // ---- phase 1: scores = Q @ K^T ----
    const int wm = warp & 1;   // 2 warps over M (32 rows)
    const int wn = warp >> 1;  // 4 warps over N (128 cols)
    float acc[2][16][4];
    #pragma unroll
    for (int i = 0; i < 2; i++)
        #pragma unroll
        for (int j = 0; j < 16; j++)
            #pragma unroll
            for (int k = 0; k < 4; k++) acc[i][j][k] = 0.f;

    #pragma unroll 1
    for (int kk = 0; kk < DK; kk += 8) {
        unsigned a[2][4];
        #pragma unroll
        for (int mf = 0; mf < 2; mf++) {
            int rb = wm * 32 + mf * 16 + gid;
            a[mf][0] = f2tf(vb0[rb * AST + kk + tig]);
            a[mf][1] = f2tf(vb0[(rb + 8) * AST + kk + tig]);
            a[mf][2] = f2tf(vb0[rb * AST + kk + 4 + tig]);
            a[mf][3] = f2tf(vb0[(rb + 8) * AST + kk + 4 + tig]);
        }
        #pragma unroll
        for (int nf = 0; nf < 16; nf++) {
            int nb = wn * 128 + nf * 8 + gid;
            unsigned bb0 = f2tf(sK[nb * AST + kk + tig]);
            unsigned bb1 = f2tf(sK[nb * AST + kk + 4 + tig]);
            mma8(acc[0][nf], a[0], bb0, bb1);
            mma8(acc[1][nf], a[1], bb0, bb1);
        }
    }
    __syncthreads();   // K/Q dead; overlay scores on sK

    // prefetch V chunks 0,1 (land during blend + softmax)
    {
        #pragma unroll
        for (int j = 0; j < 4; j++) {
            int idx = tid + 256 * j;
            int r = idx >> 4, c = (idx & 15) << 2;
            cp16(vb1 + r * AST + c, vsrcb + r * DK + c);
        }
        cp_commit();
        #pragma unroll
        for (int j = 0; j < 4; j++) {
            int idx = tid + 256 * j;
            int r = idx >> 4, c = (idx & 15) << 2;
            cp16(vb2 + r * AST + c, vsrcb + (64 + r) * DK + c);
        }
        cp_commit();
    }

    // ---- score epilogue: scale + attn_mask + dependency blend -> sK ----
    {
        const float* hvp = help_vals + ((size_t)bh * SS + q0) * SS;
        const int*   hmp = help_mask + ((size_t)bh * SS + q0) * SS;
        const int*   amp = amask + ((size_t)b * SS + q0) * SS;
        #pragma unroll
        for (int mf = 0; mf < 2; mf++) {
            #pragma unroll
            for (int rr = 0; rr < 2; rr++) {
                int lm = wm * 32 + mf * 16 + gid + rr * 8;
                #pragma unroll
                for (int nf = 0; nf < 16; nf++) {
                    int ln = wn * 128 + nf * 8 + tig * 2;
                    size_t off = (size_t)lm * SS + ln;
                    float2 hv2 = *reinterpret_cast<const float2*>(hvp + off);
                    int2   hm2 = *reinterpret_cast<const int2*>(hmp + off);
                    int2   am2 = *reinterpret_cast<const int2*>(amp + off);
                    float s0 = am2.x ? NEG_INF_F : acc[mf][nf][rr * 2 + 0] * 0.125f;
                    float s1 = am2.y ? NEG_INF_F : acc[mf][nf][rr * 2 + 1] * 0.125f;
                    if (hm2.x && hv2.x > HTHRESH_F) s0 = 0.5f * hv2.x + 0.5f * s0;
                    if (hm2.y && hv2.y > HTHRESH_F) s1 = 0.5f * hv2.y + 0.5f * s1;
                    sK[lm * 516 + ln]     = s0;
                    sK[lm * 516 + ln + 1] = s1;
                }
            }
        }
    }
    __syncthreads();

    // ---- phase 2: softmax per row; write attn; keep tf32-rounded P ----
    {
        float* aout = attn_out + ((size_t)bh * SS + q0) * SS;
        #pragma unroll 1
        for (int j = 0; j < 8; j++) {
            int r = warp * 8 + j;
            float* row = &sK[r * 516];
            float vals[16];
            float mx = -3e38f;
            #pragma unroll
            for (int i = 0; i < 16; i++) { vals[i] = row[lane + 32 * i]; mx = fmaxf(mx, vals[i]); }
            #pragma unroll
            for (int o = 16; o > 0; o >>= 1) mx = fmaxf(mx, __shfl_xor_sync(0xffffffffu, mx, o));
            float sum = 0.f;
            #pragma unroll
            for (int i = 0; i < 16; i++) { vals[i] = __expf(vals[i] - mx); sum += vals[i]; }
            #pragma unroll
            for (int o = 16; o > 0; o >>= 1) sum += __shfl_xor_sync(0xffffffffu, sum, o);
            float inv = 1.0f / sum;
            #pragma unroll
            for (int i = 0; i < 16; i++) {
                float p = vals[i] * inv;
                aout[(size_t)r * SS + lane + 32 * i] = p;
                row[lane + 32 * i] = tf2f(p);
            }
        }
    }

    // ---- phase 3: ctx = P @ V, triple-buffered V chunks ----
    const int wm3 = warp & 3;   // 4 warps over M (16 rows)
    const int wn3 = warp >> 2;  // 2 warps over N (32 cols)
    float cacc[4][4];
    #pragma unroll
    for (int j = 0; j < 4; j++)
        #pragma unroll
        for (int k = 0; k < 4; k++) cacc[j][k] = 0.f;

    float* vbuf[3] = {vb0, vb1, vb2};
    #pragma unroll 1
    for (int ch = 0; ch < 8; ch++) {
        cp_wait<1>();
        __syncthreads();   // chunk ch ready; buffer (ch+2)%3 consumed
        if (ch + 2 < 8) {
            float* dstb = vbuf[(ch + 3) % 3];
            const float* src = vsrcb + (size_t)(ch + 2) * 64 * DK;
            #pragma unroll
            for (int j = 0; j < 4; j++) {
                int idx = tid + 256 * j;
                int r = idx >> 4, c = (idx & 15) << 2;
                cp16(dstb + r * AST + c, src + r * DK + c);
            }
        }
        cp_commit();

        const float* sV = vbuf[(ch + 1) % 3];
        #pragma unroll 1
        for (int kk = 0; kk < 64; kk += 8) {
            unsigned a[4];
            int rb = wm3 * 16 + gid;
            int col = ch * 64 + kk + tig;
            a[0] = __float_as_uint(sK[rb * 516 + col]);
            a[1] = __float_as_uint(sK[(rb + 8) * 516 + col]);
            a[2] = __float_as_uint(sK[rb * 516 + col + 4]);
            a[3] = __float_as_uint(sK[(rb + 8) * 516 + col + 4]);
            #pragma unroll
            for (int nf = 0; nf < 4; nf++) {
                int nb = wn3 * 32 + nf * 8 + gid;
                unsigned bb0 = f2tf(sV[(kk + tig) * AST + nb]);
                unsigned bb1 = f2tf(sV[(kk + 4 + tig) * AST + nb]);
                mma8(cacc[nf], a, bb0, bb1);
            }
        }
    }

    // write ctx tile -> g_ctx [m = b*S+s][h*64+d]
    #pragma unroll
    for (int rr = 0; rr < 2; rr++) {
        int s = q0 + wm3 * 16 + gid + rr * 8;
        #pragma unroll
        for (int nf = 0; nf < 4; nf++) {
            int d = wn3 * 32 + nf * 8 + tig * 2;
            *reinterpret_cast<float2*>(
                &g_ctx[((size_t)b * SS + s) * DD + h * DK + d]) =
                make_float2(cacc[nf][rr * 2], cacc[nf][rr * 2 + 1]);
        }
    }
}

// =====================================================================
// LayerNorm: one warp per row, no cross-warp reduction.
// =====================================================================
__global__ __launch_bounds__(256)
void ln_kernel(const float* __restrict__ ln_g, const float* __restrict__ ln_b,
               float* __restrict__ y_out)
{
    const int warp = threadIdx.x >> 5, lane = threadIdx.x & 31;
    const int r = blockIdx.x * 8 + warp;
    const float4* row4 = reinterpret_cast<const float4*>(g_res + (size_t)r * DD);
    float4 v[8];
    float s = 0.f, q = 0.f;
    #pragma unroll
    for (int i = 0; i < 8; i++) {
        v[i] = row4[lane + 32 * i];
        s += v[i].x + v[i].y + v[i].z + v[i].w;
        q += v[i].x * v[i].x + v[i].y * v[i].y + v[i].z * v[i].z + v[i].w * v[i].w;
    }
    #pragma unroll
    for (int o = 16; o > 0; o >>= 1) {
        s += __shfl_xor_sync(0xffffffffu, s, o);
        q += __shfl_xor_sync(0xffffffffu, q, o);
    }
    float mean = s * (1.0f / 1024.0f);
    float var  = q * (1.0f / 1024.0f) - mean * mean;
    float rstd = rsqrtf(var + 1e-5f);
    float4* out4 = reinterpret_cast<float4*>(y_out + (size_t)r * DD);
    #pragma unroll
    for (int i = 0; i < 8; i++) {
        float4 g4 = reinterpret_cast<const float4*>(ln_g)[lane + 32 * i];
        float4 b4 = reinterpret_cast<const float4*>(ln_b)[lane + 32 * i];
        float4 o;
        o.x = (v[i].x - mean) * rstd * g4.x + b4.x;
        o.y = (v[i].y - mean) * rstd * g4.y + b4.y;
        o.z = (v[i].z - mean) * rstd * g4.z + b4.z;
        o.w = (v[i].w - mean) * rstd * g4.w + b4.w;
        out4[lane + 32 * i] = o;
    }
}

// =====================================================================
extern "C" void kernel_launch(void* const* d_in, const int* in_sizes, int n_in,
                              void* d_out, int out_size)
{
    const float* x    = (const float*)d_in[0];
    const float* Wq   = (const float*)d_in[1];
    const float* bq   = (const float*)d_in[2];
    const float* Wk   = (const float*)d_in[3];
    const float* bk   = (const float*)d_in[4];
    const float* Wv   = (const float*)d_in[5];
    const float* bv   = (const float*)d_in[6];
    const float* Wo   = (const float*)d_in[7];
    const float* bo   = (const float*)d_in[8];
    const float* ln_g = (const float*)d_in[9];
    const float* ln_b = (const float*)d_in[10];
    const float* hv   = (const float*)d_in[11];
    const int*   hm   = (const int*)d_in[12];
    const int*   am   = (const int*)d_in[13];

    float* out = (float*)d_out;
    float* y_out    = out;                          // [B,S,D]
    float* attn_out = out + (size_t)MTOT * DD;      // [B,H,S,S]

    cudaFuncSetAttribute(gemm_tf32_kernel<0>,
                         cudaFuncAttributeMaxDynamicSharedMemorySize, GEMM_SMEM_BYTES);
    cudaFuncSetAttribute(gemm_tf32_kernel<1>,
                         cudaFuncAttributeMaxDynamicSharedMemorySize, GEMM_SMEM_BYTES);
    cudaFuncSetAttribute(attn_fused_kernel,
                         cudaFuncAttributeMaxDynamicSharedMemorySize, ATTN_SMEM_BYTES);

    // 1) QKV projections
    gemm_tf32_kernel<0><<<dim3(32, 8, 3), 256, GEMM_SMEM_BYTES>>>(
        x, Wq, Wk, Wv, bq, bk, bv, nullptr);
    // 2) fused attention (scores + blend + softmax + attn write + ctx)
    attn_fused_kernel<<<dim3(BHTOT, 8), 256, ATTN_SMEM_BYTES>>>(hv, hm, am, attn_out);
    // 3) out projection + bias + residual
    gemm_tf32_kernel<1><<<dim3(32, 8, 1), 256, GEMM_SMEM_BYTES>>>(
        x, Wo, Wo, Wo, bo, bo, bo, x);
    // 4) LayerNorm -> y
    ln_kernel<<<dim3(MTOT / 8), 256>>>(ln_g, ln_b, y_out);
}

// round 6
// speedup vs baseline: 1.5712x; 1.5712x over previous
#include <cuda_runtime.h>
#include <cstdint>

#define NEG_INF_F (-1e9f)
#define HTHRESH_F (-1e8f)

// B=8, S=512, D=1024, H=16, DK=64
#define BB 8
#define SS 512
#define DD 1024
#define HH 16
#define DK 64
#define MTOT (BB*SS)          // 4096
#define BHTOT (BB*HH)         // 128

// -------- scratch (device globals; no cudaMalloc allowed) --------
__device__ float g_q[BB*HH*SS*DK];
__device__ float g_k[BB*HH*SS*DK];
__device__ float g_v[BB*HH*SS*DK];
__device__ float g_ctx[MTOT*DD];
__device__ float g_res[MTOT*DD];
// tf32-pre-rounded operands (rounding hoisted out of GEMM inner loops)
__device__ float g_xr[MTOT*DD];
__device__ float g_wqr[DD*DD];
__device__ float g_wkr[DD*DD];
__device__ float g_wvr[DD*DD];
__device__ float g_wor[DD*DD];

// -------- helpers --------
__device__ __forceinline__ unsigned f2tf(float f) {
    unsigned u;
    asm("cvt.rna.tf32.f32 %0, %1;" : "=r"(u) : "f"(f));
    return u;
}
__device__ __forceinline__ float tf2f(float f) {
    return __uint_as_float(f2tf(f));
}
__device__ __forceinline__ void mma8(float c[4], const unsigned a[4], unsigned b0, unsigned b1) {
    asm volatile(
        "mma.sync.aligned.m16n8k8.row.col.f32.tf32.tf32.f32 "
        "{%0,%1,%2,%3}, {%4,%5,%6,%7}, {%8,%9}, {%0,%1,%2,%3};\n"
        : "+f"(c[0]), "+f"(c[1]), "+f"(c[2]), "+f"(c[3])
        : "r"(a[0]), "r"(a[1]), "r"(a[2]), "r"(a[3]), "r"(b0), "r"(b1));
}
__device__ __forceinline__ void cp16(float* smem_dst, const float* gsrc) {
    unsigned d = (unsigned)__cvta_generic_to_shared(smem_dst);
    asm volatile("cp.async.cg.shared.global [%0], [%1], 16;\n" :: "r"(d), "l"(gsrc));
}
__device__ __forceinline__ void cp_commit() {
    asm volatile("cp.async.commit_group;\n");
}
template<int N>
__device__ __forceinline__ void cp_wait() {
    asm volatile("cp.async.wait_group %0;\n" :: "n"(N));
}

// =====================================================================
// Prep: tf32-round x and the four weight matrices into scratch copies.
// grid = (blocks, 5): y=0 -> x (1M float4), y=1..4 -> weights (256K each)
// =====================================================================
__global__ __launch_bounds__(256)
void prep_round_kernel(const float* __restrict__ x,
                       const float* __restrict__ Wq, const float* __restrict__ Wk,
                       const float* __restrict__ Wv, const float* __restrict__ Wo)
{
    const int t = blockIdx.y;
    const float4* src;
    float4* dst;
    int n4;
    if (t == 0)      { src = (const float4*)x;  dst = (float4*)g_xr;  n4 = MTOT * DD / 4; }
    else if (t == 1) { src = (const float4*)Wq; dst = (float4*)g_wqr; n4 = DD * DD / 4; }
    else if (t == 2) { src = (const float4*)Wk; dst = (float4*)g_wkr; n4 = DD * DD / 4; }
    else if (t == 3) { src = (const float4*)Wv; dst = (float4*)g_wvr; n4 = DD * DD / 4; }
    else             { src = (const float4*)Wo; dst = (float4*)g_wor; n4 = DD * DD / 4; }
    for (int i = blockIdx.x * blockDim.x + threadIdx.x; i < n4;
         i += gridDim.x * blockDim.x) {
        float4 v = src[i];
        v.x = tf2f(v.x); v.y = tf2f(v.y); v.z = tf2f(v.z); v.w = tf2f(v.w);
        dst[i] = v;
    }
}

// =====================================================================
// GEMM: C[4096,1024] = A @ W (+bias [+residual])
// 128x128x32 tiles, 3-stage cp.async pipeline, XOR-swizzled smem.
// Operands are pre-rounded tf32; inner loop has NO conversions.
// MODE 0: A=g_xr, W/bias by z, epilogue stores tf32-rounded q/k/v.
// MODE 1: A=g_ctx (pre-rounded), W=g_wor, + bias + residual(x raw).
// =====================================================================
#define GBM 128
#define GBN 128
#define GBK 32
#define GST 3
#define GEMM_SMEM_BYTES (GST * (GBM*GBK + GBK*GBN) * 4)   // 98304

template<int MODE>
__global__ __launch_bounds__(256, 2)
void gemm_tf32_kernel(const float* __restrict__ bias0, const float* __restrict__ bias1,
                      const float* __restrict__ bias2,
                      const float* __restrict__ xres)
{
    extern __shared__ float gsm[];
    float* sA = gsm;                       // [GST][128*32]
    float* sB = gsm + GST * (GBM * GBK);   // [GST][32*128]

    const int z = blockIdx.z;
    const float* W    = (MODE == 1) ? g_wor : ((z == 0) ? g_wqr : (z == 1 ? g_wkr : g_wvr));
    const float* bias = (z == 0) ? bias0 : (z == 1 ? bias1 : bias2);
    const float* A    = (MODE == 0) ? g_xr : g_ctx;
    float* dst;
    if (MODE == 0) dst = (z == 0) ? g_q : (z == 1 ? g_k : g_v);
    else           dst = g_res;

    const int m0 = blockIdx.x * GBM;
    const int n0 = blockIdx.y * GBN;
    const int tid = threadIdx.x;
    const int warp = tid >> 5, lane = tid & 31, gid = lane >> 2, tig = lane & 3;
    const int wm = warp & 1, wn = warp >> 1;    // 2 x 4 warp grid; warp tile 64x32

    float acc[4][4][4];
    #pragma unroll
    for (int i = 0; i < 4; i++)
        #pragma unroll
        for (int j = 0; j < 4; j++)
            #pragma unroll
            for (int k = 0; k < 4; k++) acc[i][j][k] = 0.f;

    // ---- tile loader (cp.async, swizzled) ----
    auto load_tile = [&](int st, int kt) {
        float* dA = sA + st * (GBM * GBK);
        float* dB = sB + st * (GBK * GBN);
        #pragma unroll
        for (int j = 0; j < 4; j++) {            // A: 128 rows x 8 chunks
            int idx = tid + 256 * j;
            int r = idx >> 3, c = idx & 7;
            cp16(dA + r * 32 + ((c ^ (r & 7)) << 2),
                 A + (size_t)(m0 + r) * DD + kt + (c << 2));
        }
        #pragma unroll
        for (int j = 0; j < 4; j++) {            // B: 32 rows x 32 chunks
            int idx = tid + 256 * j;
            int r = idx >> 5, c = idx & 31;
            cp16(dB + r * 128 + ((c ^ (r & 7)) << 2),
                 W + (size_t)(kt + r) * DD + n0 + (c << 2));
        }
    };

    // prologue: stages 0..GST-2
    #pragma unroll
    for (int s = 0; s < GST - 1; s++) { load_tile(s, s * GBK); cp_commit(); }

    const int NIT = DD / GBK;   // 32
    for (int it = 0; it < NIT; it++) {
        cp_wait<GST - 2>();
        __syncthreads();
        int nxt = it + GST - 1;
        if (nxt < NIT) load_tile(nxt % GST, nxt * GBK);
        cp_commit();

        const float* tA = sA + (it % GST) * (GBM * GBK);
        const float* tB = sB + (it % GST) * (GBK * GBN);
        #pragma unroll
        for (int kk = 0; kk < GBK; kk += 8) {
            unsigned a[4][4];
            const int c0 = kk >> 2;
            #pragma unroll
            for (int mf = 0; mf < 4; mf++) {
                int R = wm * 64 + mf * 16 + gid;     // R&7 == gid
                a[mf][0] = __float_as_uint(tA[R * 32 + ((c0 ^ gid) << 2) + tig]);
                a[mf][1] = __float_as_uint(tA[(R + 8) * 32 + ((c0 ^ gid) << 2) + tig]);
                a[mf][2] = __float_as_uint(tA[R * 32 + (((c0 + 1) ^ gid) << 2) + tig]);
                a[mf][3] = __float_as_uint(tA[(R + 8) * 32 + (((c0 + 1) ^ gid) << 2) + tig]);
            }
            #pragma unroll
            for (int nf = 0; nf < 4; nf++) {
                int nb = wn * 32 + nf * 8 + gid;
                int cc = nb >> 2, el = nb & 3;
                int k0 = kk + tig, k1 = kk + 4 + tig;
                unsigned b0 = __float_as_uint(tB[k0 * 128 + ((cc ^ (k0 & 7)) << 2) + el]);
                unsigned b1 = __float_as_uint(tB[k1 * 128 + ((cc ^ (k1 & 7)) << 2) + el]);
                #pragma unroll
                for (int mf = 0; mf < 4; mf++) mma8(acc[mf][nf], a[mf], b0, b1);
            }
        }
    }

    // epilogue
    #pragma unroll
    for (int mf = 0; mf < 4; mf++) {
        #pragma unroll
        for (int rr = 0; rr < 2; rr++) {
            int m = m0 + wm * 64 + mf * 16 + gid + rr * 8;
            #pragma unroll
            for (int nf = 0; nf < 4; nf++) {
                int n = n0 + wn * 32 + nf * 8 + tig * 2;
                float v0 = acc[mf][nf][rr * 2 + 0] + bias[n];
                float v1 = acc[mf][nf][rr * 2 + 1] + bias[n + 1];
                if (MODE == 0) {
                    // store tf32-rounded q/k/v so attention loads raw
                    int bidx = m >> 9, s = m & 511, hh = n >> 6, d = n & 63;
                    *reinterpret_cast<float2*>(
                        &dst[(((size_t)bidx * HH + hh) * SS + s) * DK + d]) =
                        make_float2(tf2f(v0), tf2f(v1));
                } else {
                    v0 += xres[(size_t)m * DD + n];
                    v1 += xres[(size_t)m * DD + n + 1];
                    *reinterpret_cast<float2*>(&dst[(size_t)m * DD + n]) = make_float2(v0, v1);
                }
            }
        }
    }
}

// =====================================================================
// Fused attention kernel: block = (b,h, 64-row q-tile), 256 threads.
// q/k/v arrive pre-rounded (tf32 values in fp32 storage) -> raw frag loads.
//   phase1: S = Q @ K^T * 0.125
//   phase2: row softmax; attn (full fp32) to gmem; tf32-rounded P in smem
//   phase3: ctx = P @ V, V triple-buffered; ctx stored tf32-rounded
// =====================================================================
#define AST 72
#define SK_FLOATS (512 * AST)        // 36864
#define VB_FLOATS (64 * AST)         // 4608
#define ATTN_SMEM_BYTES ((SK_FLOATS + 3 * VB_FLOATS) * 4)   // 202752

__global__ __launch_bounds__(256)
void attn_fused_kernel(const float* __restrict__ help_vals,
                       const int* __restrict__ help_mask,
                       const int* __restrict__ amask,
                       float* __restrict__ attn_out)
{
    extern __shared__ float smem[];
    float* sK = smem;                               // K tile / scores (stride 516)
    float* vb0 = smem + SK_FLOATS;                  // Q, then V chunks
    float* vb1 = vb0 + VB_FLOATS;
    float* vb2 = vb1 + VB_FLOATS;

    const int bh = blockIdx.x;
    const int b = bh >> 4;
    const int h = bh & 15;
    const int q0 = blockIdx.y * 64;
    const int tid = threadIdx.x;
    const int warp = tid >> 5, lane = tid & 31, gid = lane >> 2, tig = lane & 3;

    const float* vsrcb = g_v + (size_t)bh * SS * DK;

    // ---- async load Q tile (into vb0) and full K ----
    {
        const float* qsrc = g_q + ((size_t)bh * SS + q0) * DK;
        #pragma unroll
        for (int j = 0; j < 4; j++) {
            int idx = tid + 256 * j;
            int r = idx >> 4, c = (idx & 15) << 2;
            cp16(vb0 + r * AST + c, qsrc + r * DK + c);
        }
        const float* ksrc = g_k + (size_t)bh * SS * DK;
        #pragma unroll
        for (int j = 0; j < 32; j++) {
            int idx = tid + 256 * j;
            int r = idx >> 4, c = (idx & 15) << 2;
            cp16(sK + r * AST + c, ksrc + r * DK + c);
        }
        cp_commit();
        cp_wait<0>();
        __syncthreads();
    }

    // ---- phase 1: scores = Q @ K^T ----
    const int wm = warp & 1;   // 2 warps over M (32 rows)
    const int wn = warp >> 1;  // 4 warps over N (128 cols)
    float acc[2][16][4];
    #pragma unroll
    for (int i = 0; i < 2; i++)
        #pragma unroll
        for (int j = 0; j < 16; j++)
            #pragma unroll
            for (int k = 0; k < 4; k++) acc[i][j][k] = 0.f;

    #pragma unroll 1
    for (int kk = 0; kk < DK; kk += 8) {
        unsigned a[2][4];
        #pragma unroll
        for (int mf = 0; mf < 2; mf++) {
            int rb = wm * 32 + mf * 16 + gid;
            a[mf][0] = __float_as_uint(vb0[rb * AST + kk + tig]);
            a[mf][1] = __float_as_uint(vb0[(rb + 8) * AST + kk + tig]);
            a[mf][2] = __float_as_uint(vb0[rb * AST + kk + 4 + tig]);
            a[mf][3] = __float_as_uint(vb0[(rb + 8) * AST + kk + 4 + tig]);
        }
        #pragma unroll
        for (int nf = 0; nf < 16; nf++) {
            int nb = wn * 128 + nf * 8 + gid;
            unsigned bb0 = __float_as_uint(sK[nb * AST + kk + tig]);
            unsigned bb1 = __float_as_uint(sK[nb * AST + kk + 4 + tig]);
            mma8(acc[0][nf], a[0], bb0, bb1);
            mma8(acc[1][nf], a[1], bb0, bb1);
        }
    }
    __syncthreads();   // K/Q dead; overlay scores on sK

    // prefetch V chunks 0,1 (land during blend + softmax)
    {
        #pragma unroll
        for (int j = 0; j < 4; j++) {
            int idx = tid + 256 * j;
            int r = idx >> 4, c = (idx & 15) << 2;
            cp16(vb1 + r * AST + c, vsrcb + r * DK + c);
        }
        cp_commit();
        #pragma unroll
        for (int j = 0; j < 4; j++) {
            int idx = tid + 256 * j;
            int r = idx >> 4, c = (idx & 15) << 2;
            cp16(vb2 + r * AST + c, vsrcb + (64 + r) * DK + c);
        }
        cp_commit();
    }

    // ---- score epilogue: scale + attn_mask + dependency blend -> sK ----
    {
        const float* hvp = help_vals + ((size_t)bh * SS + q0) * SS;
        const int*   hmp = help_mask + ((size_t)bh * SS + q0) * SS;
        const int*   amp = amask + ((size_t)b * SS + q0) * SS;
        #pragma unroll
        for (int mf = 0; mf < 2; mf++) {
            #pragma unroll
            for (int rr = 0; rr < 2; rr++) {
                int lm = wm * 32 + mf * 16 + gid + rr * 8;
                #pragma unroll
                for (int nf = 0; nf < 16; nf++) {
                    int ln = wn * 128 + nf * 8 + tig * 2;
                    size_t off = (size_t)lm * SS + ln;
                    float2 hv2 = *reinterpret_cast<const float2*>(hvp + off);
                    int2   hm2 = *reinterpret_cast<const int2*>(hmp + off);
                    int2   am2 = *reinterpret_cast<const int2*>(amp + off);
                    float s0 = am2.x ? NEG_INF_F : acc[mf][nf][rr * 2 + 0] * 0.125f;
                    float s1 = am2.y ? NEG_INF_F : acc[mf][nf][rr * 2 + 1] * 0.125f;
                    if (hm2.x && hv2.x > HTHRESH_F) s0 = 0.5f * hv2.x + 0.5f * s0;
                    if (hm2.y && hv2.y > HTHRESH_F) s1 = 0.5f * hv2.y + 0.5f * s1;
                    sK[lm * 516 + ln]     = s0;
                    sK[lm * 516 + ln + 1] = s1;
                }
            }
        }
    }
    __syncthreads();

    // ---- phase 2: softmax per row; write attn; keep tf32-rounded P ----
    {
        float* aout = attn_out + ((size_t)bh * SS + q0) * SS;
        #pragma unroll 1
        for (int j = 0; j < 8; j++) {
            int r = warp * 8 + j;
            float* row = &sK[r * 516];
            float vals[16];
            float mx = -3e38f;
            #pragma unroll
            for (int i = 0; i < 16; i++) { vals[i] = row[lane + 32 * i]; mx = fmaxf(mx, vals[i]); }
            #pragma unroll
            for (int o = 16; o > 0; o >>= 1) mx = fmaxf(mx, __shfl_xor_sync(0xffffffffu, mx, o));
            float sum = 0.f;
            #pragma unroll
            for (int i = 0; i < 16; i++) { vals[i] = __expf(vals[i] - mx); sum += vals[i]; }
            #pragma unroll
            for (int o = 16; o > 0; o >>= 1) sum += __shfl_xor_sync(0xffffffffu, sum, o);
            float inv = 1.0f / sum;
            #pragma unroll
            for (int i = 0; i < 16; i++) {
                float p = vals[i] * inv;
                aout[(size_t)r * SS + lane + 32 * i] = p;
                row[lane + 32 * i] = tf2f(p);
            }
        }
    }

    // ---- phase 3: ctx = P @ V, triple-buffered V chunks ----
    const int wm3 = warp & 3;   // 4 warps over M (16 rows)
    const int wn3 = warp >> 2;  // 2 warps over N (32 cols)
    float cacc[4][4];
    #pragma unroll
    for (int j = 0; j < 4; j++)
        #pragma unroll
        for (int k = 0; k < 4; k++) cacc[j][k] = 0.f;

    float* vbuf[3] = {vb0, vb1, vb2};
    #pragma unroll 1
    for (int ch = 0; ch < 8; ch++) {
        cp_wait<1>();
        __syncthreads();   // chunk ch ready; buffer (ch+2)%3 consumed
        if (ch + 2 < 8) {
            float* dstb = vbuf[(ch + 3) % 3];
            const float* src = vsrcb + (size_t)(ch + 2) * 64 * DK;
            #pragma unroll
            for (int j = 0; j < 4; j++) {
                int idx = tid + 256 * j;
                int r = idx >> 4, c = (idx & 15) << 2;
                cp16(dstb + r * AST + c, src + r * DK + c);
            }
        }
        cp_commit();

        const float* sV = vbuf[(ch + 1) % 3];
        #pragma unroll 1
        for (int kk = 0; kk < 64; kk += 8) {
            unsigned a[4];
            int rb = wm3 * 16 + gid;
            int col = ch * 64 + kk + tig;
            a[0] = __float_as_uint(sK[rb * 516 + col]);
            a[1] = __float_as_uint(sK[(rb + 8) * 516 + col]);
            a[2] = __float_as_uint(sK[rb * 516 + col + 4]);
            a[3] = __float_as_uint(sK[(rb + 8) * 516 + col + 4]);
            #pragma unroll
            for (int nf = 0; nf < 4; nf++) {
                int nb = wn3 * 32 + nf * 8 + gid;
                unsigned bb0 = __float_as_uint(sV[(kk + tig) * AST + nb]);
                unsigned bb1 = __float_as_uint(sV[(kk + 4 + tig) * AST + nb]);
                mma8(cacc[nf], a, bb0, bb1);
            }
        }
    }

    // write tf32-rounded ctx tile -> g_ctx [m = b*S+s][h*64+d]
    #pragma unroll
    for (int rr = 0; rr < 2; rr++) {
        int s = q0 + wm3 * 16 + gid + rr * 8;
        #pragma unroll
        for (int nf = 0; nf < 4; nf++) {
            int d = wn3 * 32 + nf * 8 + tig * 2;
            *reinterpret_cast<float2*>(
                &g_ctx[((size_t)b * SS + s) * DD + h * DK + d]) =
                make_float2(tf2f(cacc[nf][rr * 2]), tf2f(cacc[nf][rr * 2 + 1]));
        }
    }
}

// =====================================================================
// LayerNorm over rows of g_res -> y output (block per row, float4)
// =====================================================================
__global__ __launch_bounds__(256)
void ln_kernel(const float* __restrict__ ln_g, const float* __restrict__ ln_b,
               float* __restrict__ y_out)
{
    __shared__ float rs[8], rq[8];
    const int r = blockIdx.x, t = threadIdx.x;
    const float4* row4 = reinterpret_cast<const float4*>(g_res + (size_t)r * DD);
    float4 v = row4[t];
    float s = v.x + v.y + v.z + v.w;
    float q = v.x * v.x + v.y * v.y + v.z * v.z + v.w * v.w;
    #pragma unroll
    for (int o = 16; o > 0; o >>= 1) {
        s += __shfl_xor_sync(0xffffffffu, s, o);
        q += __shfl_xor_sync(0xffffffffu, q, o);
    }
    if ((t & 31) == 0) { rs[t >> 5] = s; rq[t >> 5] = q; }
    __syncthreads();
    if (t < 32) {
        float ss = (t < 8) ? rs[t] : 0.f;
        float qq = (t < 8) ? rq[t] : 0.f;
        #pragma unroll
        for (int o = 4; o > 0; o >>= 1) {
            ss += __shfl_xor_sync(0xffffffffu, ss, o);
            qq += __shfl_xor_sync(0xffffffffu, qq, o);
        }
        if (t == 0) { rs[0] = ss; rq[0] = qq; }
    }
    __syncthreads();
    float mean = rs[0] * (1.0f / 1024.0f);
    float var  = rq[0] * (1.0f / 1024.0f) - mean * mean;
    float rstd = rsqrtf(var + 1e-5f);
    const float4 g4 = reinterpret_cast<const float4*>(ln_g)[t];
    const float4 b4 = reinterpret_cast<const float4*>(ln_b)[t];
    float4 o;
    o.x = (v.x - mean) * rstd * g4.x + b4.x;
    o.y = (v.y - mean) * rstd * g4.y + b4.y;
    o.z = (v.z - mean) * rstd * g4.z + b4.z;
    o.w = (v.w - mean) * rstd * g4.w + b4.w;
    reinterpret_cast<float4*>(y_out + (size_t)r * DD)[t] = o;
}

// =====================================================================
extern "C" void kernel_launch(void* const* d_in, const int* in_sizes, int n_in,
                              void* d_out, int out_size)
{
    const float* x    = (const float*)d_in[0];
    const float* Wq   = (const float*)d_in[1];
    const float* bq   = (const float*)d_in[2];
    const float* Wk   = (const float*)d_in[3];
    const float* bk   = (const float*)d_in[4];
    const float* Wv   = (const float*)d_in[5];
    const float* bv   = (const float*)d_in[6];
    const float* Wo   = (const float*)d_in[7];
    const float* bo   = (const float*)d_in[8];
    const float* ln_g = (const float*)d_in[9];
    const float* ln_b = (const float*)d_in[10];
    const float* hv   = (const float*)d_in[11];
    const int*   hm   = (const int*)d_in[12];
    const int*   am   = (const int*)d_in[13];

    float* out = (float*)d_out;
    float* y_out    = out;                          // [B,S,D]
    float* attn_out = out + (size_t)MTOT * DD;      // [B,H,S,S]

    cudaFuncSetAttribute(gemm_tf32_kernel<0>,
                         cudaFuncAttributeMaxDynamicSharedMemorySize, GEMM_SMEM_BYTES);
    cudaFuncSetAttribute(gemm_tf32_kernel<1>,
                         cudaFuncAttributeMaxDynamicSharedMemorySize, GEMM_SMEM_BYTES);
    cudaFuncSetAttribute(attn_fused_kernel,
                         cudaFuncAttributeMaxDynamicSharedMemorySize, ATTN_SMEM_BYTES);

    // 0) tf32-round x and weights into scratch copies
    prep_round_kernel<<<dim3(148, 5), 256>>>(x, Wq, Wk, Wv, Wo);
    // 1) QKV projections (rounded operands; rounded q/k/v outputs)
    gemm_tf32_kernel<0><<<dim3(32, 8, 3), 256, GEMM_SMEM_BYTES>>>(bq, bk, bv, nullptr);
    // 2) fused attention (scores + blend + softmax + attn write + ctx)
    attn_fused_kernel<<<dim3(BHTOT, 8), 256, ATTN_SMEM_BYTES>>>(hv, hm, am, attn_out);
    // 3) out projection + bias + residual (raw x)
    gemm_tf32_kernel<1><<<dim3(32, 8, 1), 256, GEMM_SMEM_BYTES>>>(bo, bo, bo, x);
    // 4) LayerNorm -> y
    ln_kernel<<<dim3(MTOT), 256>>>(ln_g, ln_b, y_out);
}

// round 7
// speedup vs baseline: 1.5983x; 1.0173x over previous
#include <cuda_runtime.h>
#include <cstdint>

#define NEG_INF_F (-1e9f)
#define HTHRESH_F (-1e8f)

// B=8, S=512, D=1024, H=16, DK=64
#define BB 8
#define SS 512
#define DD 1024
#define HH 16
#define DK 64
#define MTOT (BB*SS)          // 4096
#define BHTOT (BB*HH)         // 128

// -------- scratch (device globals; no cudaMalloc allowed) --------
__device__ float g_q[BB*HH*SS*DK];
__device__ float g_k[BB*HH*SS*DK];
__device__ float g_v[BB*HH*SS*DK];
__device__ float g_ctx[MTOT*DD];
__device__ float g_res[MTOT*DD];
// tf32-pre-rounded operands (rounding hoisted out of GEMM inner loops)
__device__ float g_xr[MTOT*DD];
__device__ float g_wqr[DD*DD];
__device__ float g_wkr[DD*DD];
__device__ float g_wvr[DD*DD];
__device__ float g_wor[DD*DD];

// -------- helpers --------
__device__ __forceinline__ unsigned f2tf(float f) {
    unsigned u;
    asm("cvt.rna.tf32.f32 %0, %1;" : "=r"(u) : "f"(f));
    return u;
}
__device__ __forceinline__ float tf2f(float f) {
    return __uint_as_float(f2tf(f));
}
__device__ __forceinline__ void mma8(float c[4], const unsigned a[4], unsigned b0, unsigned b1) {
    asm volatile(
        "mma.sync.aligned.m16n8k8.row.col.f32.tf32.tf32.f32 "
        "{%0,%1,%2,%3}, {%4,%5,%6,%7}, {%8,%9}, {%0,%1,%2,%3};\n"
        : "+f"(c[0]), "+f"(c[1]), "+f"(c[2]), "+f"(c[3])
        : "r"(a[0]), "r"(a[1]), "r"(a[2]), "r"(a[3]), "r"(b0), "r"(b1));
}
// ldmatrix.x4 on 32-bit data: 4 submatrices of 8 rows x 4 fp32 (=8x8 b16).
// Thread i's address supplies row (i%8) of submatrix (i/8).
__device__ __forceinline__ void ldsm4(unsigned r[4], unsigned saddr) {
    asm volatile("ldmatrix.sync.aligned.m8n8.x4.shared.b16 {%0,%1,%2,%3}, [%4];\n"
                 : "=r"(r[0]), "=r"(r[1]), "=r"(r[2]), "=r"(r[3]) : "r"(saddr));
}
__device__ __forceinline__ void cp16(float* smem_dst, const float* gsrc) {
    unsigned d = (unsigned)__cvta_generic_to_shared(smem_dst);
    asm volatile("cp.async.cg.shared.global [%0], [%1], 16;\n" :: "r"(d), "l"(gsrc));
}
__device__ __forceinline__ void cp_commit() {
    asm volatile("cp.async.commit_group;\n");
}
template<int N>
__device__ __forceinline__ void cp_wait() {
    asm volatile("cp.async.wait_group %0;\n" :: "n"(N));
}

// =====================================================================
// Prep: tf32-round x and the four weight matrices into scratch copies.
// =====================================================================
__global__ __launch_bounds__(256)
void prep_round_kernel(const float* __restrict__ x,
                       const float* __restrict__ Wq, const float* __restrict__ Wk,
                       const float* __restrict__ Wv, const float* __restrict__ Wo)
{
    const int t = blockIdx.y;
    const float4* src;
    float4* dst;
    int n4;
    if (t == 0)      { src = (const float4*)x;  dst = (float4*)g_xr;  n4 = MTOT * DD / 4; }
    else if (t == 1) { src = (const float4*)Wq; dst = (float4*)g_wqr; n4 = DD * DD / 4; }
    else if (t == 2) { src = (const float4*)Wk; dst = (float4*)g_wkr; n4 = DD * DD / 4; }
    else if (t == 3) { src = (const float4*)Wv; dst = (float4*)g_wvr; n4 = DD * DD / 4; }
    else             { src = (const float4*)Wo; dst = (float4*)g_wor; n4 = DD * DD / 4; }
    for (int i = blockIdx.x * blockDim.x + threadIdx.x; i < n4;
         i += gridDim.x * blockDim.x) {
        float4 v = src[i];
        v.x = tf2f(v.x); v.y = tf2f(v.y); v.z = tf2f(v.z); v.w = tf2f(v.w);
        dst[i] = v;
    }
}

// =====================================================================
// GEMM: C[4096,1024] = A @ W (+bias [+residual])
// 128x128x32 tiles, 3-stage cp.async pipeline, XOR-swizzled smem.
// A-fragments via ldmatrix.x4 (4 LDSM replace 16 LDS.32 per k-step).
// MODE 0: A=g_xr, W/bias by z, epilogue stores tf32-rounded q/k/v.
// MODE 1: A=g_ctx (pre-rounded), W=g_wor, + bias + residual(x raw).
// =====================================================================
#define GBM 128
#define GBN 128
#define GBK 32
#define GST 3
#define GEMM_SMEM_BYTES (GST * (GBM*GBK + GBK*GBN) * 4)   // 98304

template<int MODE>
__global__ __launch_bounds__(256, 2)
void gemm_tf32_kernel(const float* __restrict__ bias0, const float* __restrict__ bias1,
                      const float* __restrict__ bias2,
                      const float* __restrict__ xres)
{
    extern __shared__ float gsm[];
    float* sA = gsm;                       // [GST][128*32]
    float* sB = gsm + GST * (GBM * GBK);   // [GST][32*128]

    const int z = blockIdx.z;
    const float* W    = (MODE == 1) ? g_wor : ((z == 0) ? g_wqr : (z == 1 ? g_wkr : g_wvr));
    const float* bias = (z == 0) ? bias0 : (z == 1 ? bias1 : bias2);
    const float* A    = (MODE == 0) ? g_xr : g_ctx;
    float* dst;
    if (MODE == 0) dst = (z == 0) ? g_q : (z == 1 ? g_k : g_v);
    else           dst = g_res;

    const int m0 = blockIdx.x * GBM;
    const int n0 = blockIdx.y * GBN;
    const int tid = threadIdx.x;
    const int warp = tid >> 5, lane = tid & 31, gid = lane >> 2, tig = lane & 3;
    const int wm = warp & 1, wn = warp >> 1;    // 2 x 4 warp grid; warp tile 64x32

    // ldmatrix per-thread addressing: submatrix pattern
    const int l7 = lane & 7;                 // row within submatrix
    const int lh = (lane >> 3) & 1;          // 0: rows R..R+7, 1: R+8..R+15
    const int kh = lane >> 4;                // 0: kgroup c0, 1: c0+1

    float acc[4][4][4];
    #pragma unroll
    for (int i = 0; i < 4; i++)
        #pragma unroll
        for (int j = 0; j < 4; j++)
            #pragma unroll
            for (int k = 0; k < 4; k++) acc[i][j][k] = 0.f;

    // ---- tile loader (cp.async, swizzled) ----
    auto load_tile = [&](int st, int kt) {
        float* dA = sA + st * (GBM * GBK);
        float* dB = sB + st * (GBK * GBN);
        #pragma unroll
        for (int j = 0; j < 4; j++) {            // A: 128 rows x 8 chunks
            int idx = tid + 256 * j;
            int r = idx >> 3, c = idx & 7;
            cp16(dA + r * 32 + ((c ^ (r & 7)) << 2),
                 A + (size_t)(m0 + r) * DD + kt + (c << 2));
        }
        #pragma unroll
        for (int j = 0; j < 4; j++) {            // B: 32 rows x 32 chunks
            int idx = tid + 256 * j;
            int r = idx >> 5, c = idx & 31;
            cp16(dB + r * 128 + ((c ^ (r & 7)) << 2),
                 W + (size_t)(kt + r) * DD + n0 + (c << 2));
        }
    };

    // prologue: stages 0..GST-2
    #pragma unroll
    for (int s = 0; s < GST - 1; s++) { load_tile(s, s * GBK); cp_commit(); }

    const int NIT = DD / GBK;   // 32
    for (int it = 0; it < NIT; it++) {
        cp_wait<GST - 2>();
        __syncthreads();
        int nxt = it + GST - 1;
        if (nxt < NIT) load_tile(nxt % GST, nxt * GBK);
        cp_commit();

        const float* tA = sA + (it % GST) * (GBM * GBK);
        const float* tB = sB + (it % GST) * (GBK * GBN);
        const unsigned tAs = (unsigned)__cvta_generic_to_shared(tA);
        #pragma unroll
        for (int kk = 0; kk < GBK; kk += 8) {
            const int c0 = kk >> 2;
            unsigned a[4][4];
            #pragma unroll
            for (int mf = 0; mf < 4; mf++) {
                int row = wm * 64 + mf * 16 + lh * 8 + l7;
                unsigned saddr = tAs + ((row * 32 + (((c0 + kh) ^ l7) << 2)) << 2);
                ldsm4(a[mf], saddr);
            }
            #pragma unroll
            for (int nf = 0; nf < 4; nf++) {
                int nb = wn * 32 + nf * 8 + gid;
                int cc = nb >> 2, el = nb & 3;
                int k0 = kk + tig, k1 = kk + 4 + tig;
                unsigned b0 = __float_as_uint(tB[k0 * 128 + ((cc ^ (k0 & 7)) << 2) + el]);
                unsigned b1 = __float_as_uint(tB[k1 * 128 + ((cc ^ (k1 & 7)) << 2) + el]);
                #pragma unroll
                for (int mf = 0; mf < 4; mf++) mma8(acc[mf][nf], a[mf], b0, b1);
            }
        }
    }

    // epilogue
    #pragma unroll
    for (int mf = 0; mf < 4; mf++) {
        #pragma unroll
        for (int rr = 0; rr < 2; rr++) {
            int m = m0 + wm * 64 + mf * 16 + gid + rr * 8;
            #pragma unroll
            for (int nf = 0; nf < 4; nf++) {
                int n = n0 + wn * 32 + nf * 8 + tig * 2;
                float v0 = acc[mf][nf][rr * 2 + 0] + bias[n];
                float v1 = acc[mf][nf][rr * 2 + 1] + bias[n + 1];
                if (MODE == 0) {
                    // store tf32-rounded q/k/v so attention loads raw
                    int bidx = m >> 9, s = m & 511, hh = n >> 6, d = n & 63;
                    *reinterpret_cast<float2*>(
                        &dst[(((size_t)bidx * HH + hh) * SS + s) * DK + d]) =
                        make_float2(tf2f(v0), tf2f(v1));
                } else {
                    v0 += xres[(size_t)m * DD + n];
                    v1 += xres[(size_t)m * DD + n + 1];
                    *reinterpret_cast<float2*>(&dst[(size_t)m * DD + n]) = make_float2(v0, v1);
                }
            }
        }
    }
}

// =====================================================================
// Fused attention kernel: block = (b,h, 64-row q-tile), 256 threads.
// q/k/v arrive pre-rounded (tf32 values in fp32 storage) -> raw frag loads.
//   phase1: S = Q @ K^T * 0.125
//   blend:  software-pipelined LDG prefetch (distance 4) over hv/hm/am
//   phase2: row softmax; attn (full fp32) to gmem; tf32-rounded P in smem
//   phase3: ctx = P @ V, V triple-buffered; ctx stored tf32-rounded
// =====================================================================
#define AST 72
#define SK_FLOATS (512 * AST)        // 36864
#define VB_FLOATS (64 * AST)         // 4608
#define ATTN_SMEM_BYTES ((SK_FLOATS + 3 * VB_FLOATS) * 4)   // 202752
#define PF 4

__global__ __launch_bounds__(256)
void attn_fused_kernel(const float* __restrict__ help_vals,
                       const int* __restrict__ help_mask,
                       const int* __restrict__ amask,
                       float* __restrict__ attn_out)
{
    extern __shared__ float smem[];
    float* sK = smem;                               // K tile / scores (stride 516)
    float* vb0 = smem + SK_FLOATS;                  // Q, then V chunks
    float* vb1 = vb0 + VB_FLOATS;
    float* vb2 = vb1 + VB_FLOATS;

    const int bh = blockIdx.x;
    const int b = bh >> 4;
    const int h = bh & 15;
    const int q0 = blockIdx.y * 64;
    const int tid = threadIdx.x;
    const int warp = tid >> 5, lane = tid & 31, gid = lane >> 2, tig = lane & 3;

    const float* vsrcb = g_v + (size_t)bh * SS * DK;

    // ---- async load Q tile (into vb0) and full K ----
    {
        const float* qsrc = g_q + ((size_t)bh * SS + q0) * DK;
        #pragma unroll
        for (int j = 0; j < 4; j++) {
            int idx = tid + 256 * j;
            int r = idx >> 4, c = (idx & 15) << 2;
            cp16(vb0 + r * AST + c, qsrc + r * DK + c);
        }
        const float* ksrc = g_k + (size_t)bh * SS * DK;
        #pragma unroll
        for (int j = 0; j < 32; j++) {
            int idx = tid + 256 * j;
            int r = idx >> 4, c = (idx & 15) << 2;
            cp16(sK + r * AST + c, ksrc + r * DK + c);
        }
        cp_commit();
        cp_wait<0>();
        __syncthreads();
    }

    // ---- phase 1: scores = Q @ K^T ----
    const int wm = warp & 1;   // 2 warps over M (32 rows)
    const int wn = warp >> 1;  // 4 warps over N (128 cols)
    float acc[2][16][4];
    #pragma unroll
    for (int i = 0; i < 2; i++)
        #pragma unroll
        for (int j = 0; j < 16; j++)
            #pragma unroll
            for (int k = 0; k < 4; k++) acc[i][j][k] = 0.f;

    #pragma unroll 1
    for (int kk = 0; kk < DK; kk += 8) {
        unsigned a[2][4];
        #pragma unroll
        for (int mf = 0; mf < 2; mf++) {
            int rb = wm * 32 + mf * 16 + gid;
            a[mf][0] = __float_as_uint(vb0[rb * AST + kk + tig]);
            a[mf][1] = __float_as_uint(vb0[(rb + 8) * AST + kk + tig]);
            a[mf][2] = __float_as_uint(vb0[rb * AST + kk + 4 + tig]);
            a[mf][3] = __float_as_uint(vb0[(rb + 8) * AST + kk + 4 + tig]);
        }
        #pragma unroll
        for (int nf = 0; nf < 16; nf++) {
            int nb = wn * 128 + nf * 8 + gid;
            unsigned bb0 = __float_as_uint(sK[nb * AST + kk + tig]);
            unsigned bb1 = __float_as_uint(sK[nb * AST + kk + 4 + tig]);
            mma8(acc[0][nf], a[0], bb0, bb1);
            mma8(acc[1][nf], a[1], bb0, bb1);
        }
    }
    __syncthreads();   // K/Q dead; overlay scores on sK

    // prefetch V chunks 0,1 (land during blend + softmax)
    {
        #pragma unroll
        for (int j = 0; j < 4; j++) {
            int idx = tid + 256 * j;
            int r = idx >> 4, c = (idx & 15) << 2;
            cp16(vb1 + r * AST + c, vsrcb + r * DK + c);
        }
        cp_commit();
        #pragma unroll
        for (int j = 0; j < 4; j++) {
            int idx = tid + 256 * j;
            int r = idx >> 4, c = (idx & 15) << 2;
            cp16(vb2 + r * AST + c, vsrcb + (64 + r) * DK + c);
        }
        cp_commit();
    }

    // ---- blend: scale + attn_mask + dependency blend -> sK ----
    // software-pipelined LDG prefetch, distance PF=4
    {
        const float* hvp = help_vals + ((size_t)bh * SS + q0) * SS;
        const int*   hmp = help_mask + ((size_t)bh * SS + q0) * SS;
        const int*   amp = amask + ((size_t)b * SS + q0) * SS;
        const int base_lm = wm * 32 + gid;
        const int base_ln = wn * 128 + tig * 2;

        float2 hvb[PF]; int2 hmb[PF]; int2 amb[PF];
        #pragma unroll
        for (int i = 0; i < PF; i++) {
            int lm = base_lm + ((i >> 5) << 4) + (((i >> 4) & 1) << 3);
            int ln = base_ln + ((i & 15) << 3);
            size_t off = (size_t)lm * SS + ln;
            hvb[i] = *reinterpret_cast<const float2*>(hvp + off);
            hmb[i] = *reinterpret_cast<const int2*>(hmp + off);
            amb[i] = *reinterpret_cast<const int2*>(amp + off);
        }
        #pragma unroll
        for (int i = 0; i < 64; i++) {
            const int slot = i & (PF - 1);
            float2 hv2 = hvb[slot];
            int2   hm2 = hmb[slot];
            int2   am2 = amb[slot];
            if (i + PF < 64) {
                int j = i + PF;
                int lmp = base_lm + ((j >> 5) << 4) + (((j >> 4) & 1) << 3);
                int lnp = base_ln + ((j & 15) << 3);
                size_t offp = (size_t)lmp * SS + lnp;
                hvb[slot] = *reinterpret_cast<const float2*>(hvp + offp);
                hmb[slot] = *reinterpret_cast<const int2*>(hmp + offp);
                amb[slot] = *reinterpret_cast<const int2*>(amp + offp);
            }
            const int mf = i >> 5, rr = (i >> 4) & 1, nf = i & 15;
            const int lm = base_lm + (mf << 4) + (rr << 3);
            const int ln = base_ln + (nf << 3);
            float s0 = am2.x ? NEG_INF_F : acc[mf][nf][rr * 2 + 0] * 0.125f;
            float s1 = am2.y ? NEG_INF_F : acc[mf][nf][rr * 2 + 1] * 0.125f;
            if (hm2.x && hv2.x > HTHRESH_F) s0 = 0.5f * hv2.x + 0.5f * s0;
            if (hm2.y && hv2.y > HTHRESH_F) s1 = 0.5f * hv2.y + 0.5f * s1;
            sK[lm * 516 + ln]     = s0;
            sK[lm * 516 + ln + 1] = s1;
        }
    }
    __syncthreads();

    // ---- phase 2: softmax per row; write attn; keep tf32-rounded P ----
    {
        float* aout = attn_out + ((size_t)bh * SS + q0) * SS;
        #pragma unroll 1
        for (int j = 0; j < 8; j++) {
            int r = warp * 8 + j;
            float* row = &sK[r * 516];
            float vals[16];
            float mx = -3e38f;
            #pragma unroll
            for (int i = 0; i < 16; i++) { vals[i] = row[lane + 32 * i]; mx = fmaxf(mx, vals[i]); }
            #pragma unroll
            for (int o = 16; o > 0; o >>= 1) mx = fmaxf(mx, __shfl_xor_sync(0xffffffffu, mx, o));
            float sum = 0.f;
            #pragma unroll
            for (int i = 0; i < 16; i++) { vals[i] = __expf(vals[i] - mx); sum += vals[i]; }
            #pragma unroll
            for (int o = 16; o > 0; o >>= 1) sum += __shfl_xor_sync(0xffffffffu, sum, o);
            float inv = 1.0f / sum;
            #pragma unroll
            for (int i = 0; i < 16; i++) {
                float p = vals[i] * inv;
                aout[(size_t)r * SS + lane + 32 * i] = p;
                row[lane + 32 * i] = tf2f(p);
            }
        }
    }

    // ---- phase 3: ctx = P @ V, triple-buffered V chunks ----
    const int wm3 = warp & 3;   // 4 warps over M (16 rows)
    const int wn3 = warp >> 2;  // 2 warps over N (32 cols)
    float cacc[4][4];
    #pragma unroll
    for (int j = 0; j < 4; j++)
        #pragma unroll
        for (int k = 0; k < 4; k++) cacc[j][k] = 0.f;

    float* vbuf[3] = {vb0, vb1, vb2};
    #pragma unroll 1
    for (int ch = 0; ch < 8; ch++) {
        cp_wait<1>();
        __syncthreads();   // chunk ch ready; buffer (ch+2)%3 consumed
        if (ch + 2 < 8) {
            float* dstb = vbuf[(ch + 3) % 3];
            const float* src = vsrcb + (size_t)(ch + 2) * 64 * DK;
            #pragma unroll
            for (int j = 0; j < 4; j++) {
                int idx = tid + 256 * j;
                int r = idx >> 4, c = (idx & 15) << 2;
                cp16(dstb + r * AST + c, src + r * DK + c);
            }
        }
        cp_commit();

        const float* sV = vbuf[(ch + 1) % 3];
        #pragma unroll 1
        for (int kk = 0; kk < 64; kk += 8) {
            unsigned a[4];
            int rb = wm3 * 16 + gid;
            int col = ch * 64 + kk + tig;
            a[0] = __float_as_uint(sK[rb * 516 + col]);
            a[1] = __float_as_uint(sK[(rb + 8) * 516 + col]);
            a[2] = __float_as_uint(sK[rb * 516 + col + 4]);
            a[3] = __float_as_uint(sK[(rb + 8) * 516 + col + 4]);
            #pragma unroll
            for (int nf = 0; nf < 4; nf++) {
                int nb = wn3 * 32 + nf * 8 + gid;
                unsigned bb0 = __float_as_uint(sV[(kk + tig) * AST + nb]);
                unsigned bb1 = __float_as_uint(sV[(kk + 4 + tig) * AST + nb]);
                mma8(cacc[nf], a, bb0, bb1);
            }
        }
    }

    // write tf32-rounded ctx tile -> g_ctx [m = b*S+s][h*64+d]
    #pragma unroll
    for (int rr = 0; rr < 2; rr++) {
        int s = q0 + wm3 * 16 + gid + rr * 8;
        #pragma unroll
        for (int nf = 0; nf < 4; nf++) {
            int d = wn3 * 32 + nf * 8 + tig * 2;
            *reinterpret_cast<float2*>(
                &g_ctx[((size_t)b * SS + s) * DD + h * DK + d]) =
                make_float2(tf2f(cacc[nf][rr * 2]), tf2f(cacc[nf][rr * 2 + 1]));
        }
    }
}

// =====================================================================
// LayerNorm over rows of g_res -> y output (block per row, float4)
// =====================================================================
__global__ __launch_bounds__(256)
void ln_kernel(const float* __restrict__ ln_g, const float* __restrict__ ln_b,
               float* __restrict__ y_out)
{
    __shared__ float rs[8], rq[8];
    const int r = blockIdx.x, t = threadIdx.x;
    const float4* row4 = reinterpret_cast<const float4*>(g_res + (size_t)r * DD);
    float4 v = row4[t];
    float s = v.x + v.y + v.z + v.w;
    float q = v.x * v.x + v.y * v.y + v.z * v.z + v.w * v.w;
    #pragma unroll
    for (int o = 16; o > 0; o >>= 1) {
        s += __shfl_xor_sync(0xffffffffu, s, o);
        q += __shfl_xor_sync(0xffffffffu, q, o);
    }
    if ((t & 31) == 0) { rs[t >> 5] = s; rq[t >> 5] = q; }
    __syncthreads();
    if (t < 32) {
        float ss = (t < 8) ? rs[t] : 0.f;
        float qq = (t < 8) ? rq[t] : 0.f;
        #pragma unroll
        for (int o = 4; o > 0; o >>= 1) {
            ss += __shfl_xor_sync(0xffffffffu, ss, o);
            qq += __shfl_xor_sync(0xffffffffu, qq, o);
        }
        if (t == 0) { rs[0] = ss; rq[0] = qq; }
    }
    __syncthreads();
    float mean = rs[0] * (1.0f / 1024.0f);
    float var  = rq[0] * (1.0f / 1024.0f) - mean * mean;
    float rstd = rsqrtf(var + 1e-5f);
    const float4 g4 = reinterpret_cast<const float4*>(ln_g)[t];
    const float4 b4 = reinterpret_cast<const float4*>(ln_b)[t];
    float4 o;
    o.x = (v.x - mean) * rstd * g4.x + b4.x;
    o.y = (v.y - mean) * rstd * g4.y + b4.y;
    o.z = (v.z - mean) * rstd * g4.z + b4.z;
    o.w = (v.w - mean) * rstd * g4.w + b4.w;
    reinterpret_cast<float4*>(y_out + (size_t)r * DD)[t] = o;
}

// =====================================================================
extern "C" void kernel_launch(void* const* d_in, const int* in_sizes, int n_in,
                              void* d_out, int out_size)
{
    const float* x    = (const float*)d_in[0];
    const float* Wq   = (const float*)d_in[1];
    const float* bq   = (const float*)d_in[2];
    const float* Wk   = (const float*)d_in[3];
    const float* bk   = (const float*)d_in[4];
    const float* Wv   = (const float*)d_in[5];
    const float* bv   = (const float*)d_in[6];
    const float* Wo   = (const float*)d_in[7];
    const float* bo   = (const float*)d_in[8];
    const float* ln_g = (const float*)d_in[9];
    const float* ln_b = (const float*)d_in[10];
    const float* hv   = (const float*)d_in[11];
    const int*   hm   = (const int*)d_in[12];
    const int*   am   = (const int*)d_in[13];

    float* out = (float*)d_out;
    float* y_out    = out;                          // [B,S,D]
    float* attn_out = out + (size_t)MTOT * DD;      // [B,H,S,S]

    cudaFuncSetAttribute(gemm_tf32_kernel<0>,
                         cudaFuncAttributeMaxDynamicSharedMemorySize, GEMM_SMEM_BYTES);
    cudaFuncSetAttribute(gemm_tf32_kernel<1>,
                         cudaFuncAttributeMaxDynamicSharedMemorySize, GEMM_SMEM_BYTES);
    cudaFuncSetAttribute(attn_fused_kernel,
                         cudaFuncAttributeMaxDynamicSharedMemorySize, ATTN_SMEM_BYTES);

    // 0) tf32-round x and weights into scratch copies
    prep_round_kernel<<<dim3(148, 5), 256>>>(x, Wq, Wk, Wv, Wo);
    // 1) QKV projections (rounded operands; rounded q/k/v outputs)
    gemm_tf32_kernel<0><<<dim3(32, 8, 3), 256, GEMM_SMEM_BYTES>>>(bq, bk, bv, nullptr);
    // 2) fused attention (scores + blend + softmax + attn write + ctx)
    attn_fused_kernel<<<dim3(BHTOT, 8), 256, ATTN_SMEM_BYTES>>>(hv, hm, am, attn_out);
    // 3) out projection + bias + residual (raw x)
    gemm_tf32_kernel<1><<<dim3(32, 8, 1), 256, GEMM_SMEM_BYTES>>>(bo, bo, bo, x);
    // 4) LayerNorm -> y
    ln_kernel<<<dim3(MTOT), 256>>>(ln_g, ln_b, y_out);
}

// round 11
// speedup vs baseline: 1.6238x; 1.0159x over previous
#include <cuda_runtime.h>
#include <cstdint>

#define NEG_INF_F (-1e9f)
#define HTHRESH_F (-1e8f)

// B=8, S=512, D=1024, H=16, DK=64
#define BB 8
#define SS 512
#define DD 1024
#define HH 16
#define DK 64
#define MTOT (BB*SS)          // 4096
#define BHTOT (BB*HH)         // 128

// -------- scratch (device globals; no cudaMalloc allowed) --------
__device__ float g_q[BB*HH*SS*DK];
__device__ float g_k[BB*HH*SS*DK];
__device__ float g_v[BB*HH*SS*DK];
__device__ float g_ctx[MTOT*DD];
__device__ float g_res[MTOT*DD];
__device__ float g_xr[MTOT*DD];     // tf32-rounded x
// tf32-rounded, TRANSPOSED weights [N][K] (n-major rows for ldmatrix B-frags)
__device__ float g_wqt[DD*DD];
__device__ float g_wkt[DD*DD];
__device__ float g_wvt[DD*DD];
__device__ float g_wot[DD*DD];

// -------- helpers --------
__device__ __forceinline__ unsigned f2tf(float f) {
    unsigned u;
    asm("cvt.rna.tf32.f32 %0, %1;" : "=r"(u) : "f"(f));
    return u;
}
__device__ __forceinline__ float tf2f(float f) {
    return __uint_as_float(f2tf(f));
}
__device__ __forceinline__ void mma8(float c[4], const unsigned a[4], unsigned b0, unsigned b1) {
    asm volatile(
        "mma.sync.aligned.m16n8k8.row.col.f32.tf32.tf32.f32 "
        "{%0,%1,%2,%3}, {%4,%5,%6,%7}, {%8,%9}, {%0,%1,%2,%3};\n"
        : "+f"(c[0]), "+f"(c[1]), "+f"(c[2]), "+f"(c[3])
        : "r"(a[0]), "r"(a[1]), "r"(a[2]), "r"(a[3]), "r"(b0), "r"(b1));
}
// ldmatrix.x4 on 32-bit data: submatrix s = 8 rows x 4 dwords; lanes 8s..8s+7
// supply row addresses; output reg s: lane j holds (row j/4, dword j%4).
__device__ __forceinline__ void ldsm4(unsigned r[4], unsigned saddr) {
    asm volatile("ldmatrix.sync.aligned.m8n8.x4.shared.b16 {%0,%1,%2,%3}, [%4];\n"
                 : "=r"(r[0]), "=r"(r[1]), "=r"(r[2]), "=r"(r[3]) : "r"(saddr));
}
__device__ __forceinline__ void cp16(float* smem_dst, const float* gsrc) {
    unsigned d = (unsigned)__cvta_generic_to_shared(smem_dst);
    asm volatile("cp.async.cg.shared.global [%0], [%1], 16;\n" :: "r"(d), "l"(gsrc));
}
__device__ __forceinline__ void cp_commit() {
    asm volatile("cp.async.commit_group;\n");
}
template<int N>
__device__ __forceinline__ void cp_wait() {
    asm volatile("cp.async.wait_group %0;\n" :: "n"(N));
}

// =====================================================================
// Prep A: tf32-round x.  Prep B: tf32-round + transpose weights -> [N][K].
// =====================================================================
__global__ __launch_bounds__(256)
void prep_round_x(const float* __restrict__ x)
{
    float4* dst = (float4*)g_xr;
    const float4* src = (const float4*)x;
    const int n4 = MTOT * DD / 4;
    for (int i = blockIdx.x * blockDim.x + threadIdx.x; i < n4;
         i += gridDim.x * blockDim.x) {
        float4 v = src[i];
        v.x = tf2f(v.x); v.y = tf2f(v.y); v.z = tf2f(v.z); v.w = tf2f(v.w);
        dst[i] = v;
    }
}
__global__ __launch_bounds__(256)
void prep_transpose_w(const float* __restrict__ Wq, const float* __restrict__ Wk,
                      const float* __restrict__ Wv, const float* __restrict__ Wo)
{
    __shared__ float t[32][33];
    const int z = blockIdx.z;
    const float* W = (z == 0) ? Wq : (z == 1 ? Wk : (z == 2 ? Wv : Wo));
    float* WT = (z == 0) ? g_wqt : (z == 1 ? g_wkt : (z == 2 ? g_wvt : g_wot));
    const int k0 = blockIdx.x * 32;        // K block (rows of W)
    const int n0 = blockIdx.y * 32;        // N block (cols of W)
    const int tx = threadIdx.x & 31, ty = threadIdx.x >> 5;   // 32x8
    #pragma unroll
    for (int j = 0; j < 4; j++) {
        int k = k0 + ty + j * 8;
        t[ty + j * 8][tx] = tf2f(W[(size_t)k * DD + n0 + tx]);
    }
    __syncthreads();
    #pragma unroll
    for (int j = 0; j < 4; j++) {
        int n = n0 + ty + j * 8;
        WT[(size_t)n * DD + k0 + tx] = t[tx][ty + j * 8];
    }
}

// =====================================================================
// GEMM: C[4096,1024] = A @ W (+bias [+residual])
// 128x128x32 tiles, 3-stage cp.async pipeline, XOR-swizzled smem.
// A-frags AND B-frags via ldmatrix.x4 (B stored n-major from W^T).
// MODE 0: A=g_xr, epilogue stores tf32-rounded q/k/v scatter [B,H,S,DK].
// MODE 1: A=g_ctx (pre-rounded), + bias + residual(x raw) -> g_res.
// =====================================================================
#define GBM 128
#define GBN 128
#define GBK 32
#define GST 3
#define TILE_F (GBM * GBK)                 // 4096 floats = 16KB
#define GEMM_SMEM_BYTES (GST * TILE_F * 2 * 4)   // 98304

template<int MODE>
__global__ __launch_bounds__(256, 2)
void gemm_tf32_kernel(const float* __restrict__ bias0, const float* __restrict__ bias1,
                      const float* __restrict__ bias2,
                      const float* __restrict__ xres)
{
    extern __shared__ float gsm[];
    float* sA = gsm;                       // [GST][128 m-rows x 32 k]
    float* sB = gsm + GST * TILE_F;        // [GST][128 n-rows x 32 k]

    const int z = blockIdx.z;
    const float* WT   = (MODE == 1) ? g_wot : ((z == 0) ? g_wqt : (z == 1 ? g_wkt : g_wvt));
    const float* bias = (z == 0) ? bias0 : (z == 1 ? bias1 : bias2);
    const float* A    = (MODE == 0) ? g_xr : g_ctx;
    float* dst = (MODE == 0) ? ((z == 0) ? g_q : (z == 1 ? g_k : g_v)) : g_res;

    const int m0 = blockIdx.x * GBM;
    const int n0 = blockIdx.y * GBN;
    const int tid = threadIdx.x;
    const int warp = tid >> 5, lane = tid & 31, gid = lane >> 2, tig = lane & 3;
    const int wm = warp & 1, wn = warp >> 1;    // 2 x 4 warp grid; warp tile 64x32

    const int l7  = lane & 7;
    const int lhA = (lane >> 3) & 1;   // A row-sub (0/8)
    const int khA = lane >> 4;         // A k-group (+0/+1 dword group)
    const int khB = (lane >> 3) & 1;   // B k-group
    const int nsB = lane >> 4;         // B n-sub (0/8)

    float acc[4][4][4];
    #pragma unroll
    for (int i = 0; i < 4; i++)
        #pragma unroll
        for (int j = 0; j < 4; j++)
            #pragma unroll
            for (int k = 0; k < 4; k++) acc[i][j][k] = 0.f;

    // ---- tile loader (cp.async, swizzled; both tiles 128 rows x 8 chunks) ----
    auto load_tile = [&](int st, int kt) {
        float* dA = sA + st * TILE_F;
        float* dB = sB + st * TILE_F;
        #pragma unroll
        for (int j = 0; j < 4; j++) {            // A: row = m
            int idx = tid + 256 * j;
            int r = idx >> 3, c = idx & 7;
            cp16(dA + r * 32 + ((c ^ (r & 7)) << 2),
                 A + (size_t)(m0 + r) * DD + kt + (c << 2));
        }
        #pragma unroll
        for (int j = 0; j < 4; j++) {            // B: row = n (from W^T)
            int idx = tid + 256 * j;
            int r = idx >> 3, c = idx & 7;
            cp16(dB + r * 32 + ((c ^ (r & 7)) << 2),
                 WT + (size_t)(n0 + r) * DD + kt + (c << 2));
        }
    };

    // prologue: stages 0..GST-2
    #pragma unroll
    for (int s = 0; s < GST - 1; s++) { load_tile(s, s * GBK); cp_commit(); }

    const int NIT = DD / GBK;   // 32
    for (int it = 0; it < NIT; it++) {
        cp_wait<GST - 2>();
        __syncthreads();
        int nxt = it + GST - 1;
        if (nxt < NIT) load_tile(nxt % GST, nxt * GBK);
        cp_commit();

        const unsigned tAs = (unsigned)__cvta_generic_to_shared(sA + (it % GST) * TILE_F);
        const unsigned tBs = (unsigned)__cvta_generic_to_shared(sB + (it % GST) * TILE_F);
        #pragma unroll
        for (int kk = 0; kk < GBK; kk += 8) {
            const int c0 = kk >> 2;
            unsigned a[4][4];
            #pragma unroll
            for (int mf = 0; mf < 4; mf++) {
                int row = wm * 64 + mf * 16 + lhA * 8 + l7;
                unsigned saddr = tAs + ((row * 32 + (((c0 + khA) ^ l7) << 2)) << 2);
                ldsm4(a[mf], saddr);
            }
            unsigned b[2][4];
            #pragma unroll
            for (int p = 0; p < 2; p++) {
                int row = wn * 32 + p * 16 + nsB * 8 + l7;
                unsigned saddr = tBs + ((row * 32 + (((c0 + khB) ^ l7) << 2)) << 2);
                ldsm4(b[p], saddr);
            }
            #pragma unroll
            for (int p = 0; p < 2; p++)
                #pragma unroll
                for (int h = 0; h < 2; h++) {
                    const int nf = p * 2 + h;
                    #pragma unroll
                    for (int mf = 0; mf < 4; mf++)
                        mma8(acc[mf][nf], a[mf], b[p][2 * h], b[p][2 * h + 1]);
                }
        }
    }

    // epilogue
    #pragma unroll
    for (int mf = 0; mf < 4; mf++) {
        #pragma unroll
        for (int rr = 0; rr < 2; rr++) {
            int m = m0 + wm * 64 + mf * 16 + gid + rr * 8;
            #pragma unroll
            for (int nf = 0; nf < 4; nf++) {
                int n = n0 + wn * 32 + nf * 8 + tig * 2;
                float v0 = acc[mf][nf][rr * 2 + 0] + bias[n];
                float v1 = acc[mf][nf][rr * 2 + 1] + bias[n + 1];
                if (MODE == 0) {
                    int bidx = m >> 9, s = m & 511, hh = n >> 6, d = n & 63;
                    *reinterpret_cast<float2*>(
                        &dst[(((size_t)bidx * HH + hh) * SS + s) * DK + d]) =
                        make_float2(tf2f(v0), tf2f(v1));
                } else {
                    v0 += xres[(size_t)m * DD + n];
                    v1 += xres[(size_t)m * DD + n + 1];
                    *reinterpret_cast<float2*>(&dst[(size_t)m * DD + n]) = make_float2(v0, v1);
                }
            }
        }
    }
}

// =====================================================================
// Fused attention kernel: block = (b,h, 64-row q-tile), 256 threads.
//   phase1: S = Q @ K^T (pre-rounded operands, raw frag loads)
//   blend:  PF=8 software-pipelined __ldcs prefetch, first batch issued
//           BEFORE phase1 so mma hides the first DRAM round-trip
//   phase2: row softmax; attn via __stcs; tf32-rounded P in smem
//   phase3: ctx = P @ V, V triple-buffered; ctx stored tf32-rounded
// =====================================================================
#define AST 72
#define SK_FLOATS (512 * AST)
#define VB_FLOATS (64 * AST)
#define ATTN_SMEM_BYTES ((SK_FLOATS + 3 * VB_FLOATS) * 4)   // 202752
#define PF 8

__global__ __launch_bounds__(256)
void attn_fused_kernel(const float* __restrict__ help_vals,
                       const int* __restrict__ help_mask,
                       const int* __restrict__ amask,
                       float* __restrict__ attn_out)
{
    extern __shared__ float smem[];
    float* sK = smem;
    float* vb0 = smem + SK_FLOATS;
    float* vb1 = vb0 + VB_FLOATS;
    float* vb2 = vb1 + VB_FLOATS;

    const int bh = blockIdx.x;
    const int b = bh >> 4;
    const int h = bh & 15;
    const int q0 = blockIdx.y * 64;
    const int tid = threadIdx.x;
    const int warp = tid >> 5, lane = tid & 31, gid = lane >> 2, tig = lane & 3;

    const float* vsrcb = g_v + (size_t)bh * SS * DK;

    {
        const float* qsrc = g_q + ((size_t)bh * SS + q0) * DK;
        #pragma unroll
        for (int j = 0; j < 4; j++) {
            int idx = tid + 256 * j;
            int r = idx >> 4, c = (idx & 15) << 2;
            cp16(vb0 + r * AST + c, qsrc + r * DK + c);
        }
        const float* ksrc = g_k + (size_t)bh * SS * DK;
        #pragma unroll
        for (int j = 0; j < 32; j++) {
            int idx = tid + 256 * j;
            int r = idx >> 4, c = (idx & 15) << 2;
            cp16(sK + r * AST + c, ksrc + r * DK + c);
        }
        cp_commit();
        cp_wait<0>();
        __syncthreads();
    }

    const int wm = warp & 1;
    const int wn = warp >> 1;

    // ---- pre-issue first blend batch (overlaps phase-1 mma) ----
    const float* hvp = help_vals + ((size_t)bh * SS + q0) * SS;
    const int*   hmp = help_mask + ((size_t)bh * SS + q0) * SS;
    const int*   amp = amask + ((size_t)b * SS + q0) * SS;
    const int base_lm = wm * 32 + gid;
    const int base_ln = wn * 128 + tig * 2;

    float2 hvb[PF]; int2 hmb[PF]; int2 amb[PF];
    #pragma unroll
    for (int i = 0; i < PF; i++) {
        int lm = base_lm + ((i >> 5) << 4) + (((i >> 4) & 1) << 3);
        int ln = base_ln + ((i & 15) << 3);
        size_t off = (size_t)lm * SS + ln;
        hvb[i] = __ldcs(reinterpret_cast<const float2*>(hvp + off));
        hmb[i] = __ldcs(reinterpret_cast<const int2*>(hmp + off));
        amb[i] = __ldcs(reinterpret_cast<const int2*>(amp + off));
    }

    // ---- phase 1: scores = Q @ K^T ----
    float acc[2][16][4];
    #pragma unroll
    for (int i = 0; i < 2; i++)
        #pragma unroll
        for (int j = 0; j < 16; j++)
            #pragma unroll
            for (int k = 0; k < 4; k++) acc[i][j][k] = 0.f;

    #pragma unroll 1
    for (int kk = 0; kk < DK; kk += 8) {
        unsigned a[2][4];
        #pragma unroll
        for (int mf = 0; mf < 2; mf++) {
            int rb = wm * 32 + mf * 16 + gid;
            a[mf][0] = __float_as_uint(vb0[rb * AST + kk + tig]);
            a[mf][1] = __float_as_uint(vb0[(rb + 8) * AST + kk + tig]);
            a[mf][2] = __float_as_uint(vb0[rb * AST + kk + 4 + tig]);
            a[mf][3] = __float_as_uint(vb0[(rb + 8) * AST + kk + 4 + tig]);
        }
        #pragma unroll
        for (int nf = 0; nf < 16; nf++) {
            int nb = wn * 128 + nf * 8 + gid;
            unsigned bb0 = __float_as_uint(sK[nb * AST + kk + tig]);
            unsigned bb1 = __float_as_uint(sK[nb * AST + kk + 4 + tig]);
            mma8(acc[0][nf], a[0], bb0, bb1);
            mma8(acc[1][nf], a[1], bb0, bb1);
        }
    }
    __syncthreads();   // K/Q dead; overlay scores on sK

    // prefetch V chunks 0,1 (land during blend + softmax)
    {
        #pragma unroll
        for (int j = 0; j < 4; j++) {
            int idx = tid + 256 * j;
            int r = idx >> 4, c = (idx & 15) << 2;
            cp16(vb1 + r * AST + c, vsrcb + r * DK + c);
        }
        cp_commit();
        #pragma unroll
        for (int j = 0; j < 4; j++) {
            int idx = tid + 256 * j;
            int r = idx >> 4, c = (idx & 15) << 2;
            cp16(vb2 + r * AST + c, vsrcb + (64 + r) * DK + c);
        }
        cp_commit();
    }

    // ---- blend: scale + attn_mask + dependency blend -> sK ----
    {
        #pragma unroll
        for (int i = 0; i < 64; i++) {
            const int slot = i & (PF - 1);
            float2 hv2 = hvb[slot];
            int2   hm2 = hmb[slot];
            int2   am2 = amb[slot];
            if (i + PF < 64) {
                int j = i + PF;
                int lmp = base_lm + ((j >> 5) << 4) + (((j >> 4) & 1) << 3);
                int lnp = base_ln + ((j & 15) << 3);
                size_t offp = (size_t)lmp * SS + lnp;
                hvb[slot] = __ldcs(reinterpret_cast<const float2*>(hvp + offp));
                hmb[slot] = __ldcs(reinterpret_cast<const int2*>(hmp + offp));
                amb[slot] = __ldcs(reinterpret_cast<const int2*>(amp + offp));
            }
            const int mf = i >> 5, rr = (i >> 4) & 1, nf = i & 15;
            const int lm = base_lm + (mf << 4) + (rr << 3);
            const int ln = base_ln + (nf << 3);
            float s0 = am2.x ? NEG_INF_F : acc[mf][nf][rr * 2 + 0] * 0.125f;
            float s1 = am2.y ? NEG_INF_F : acc[mf][nf][rr * 2 + 1] * 0.125f;
            if (hm2.x && hv2.x > HTHRESH_F) s0 = 0.5f * hv2.x + 0.5f * s0;
            if (hm2.y && hv2.y > HTHRESH_F) s1 = 0.5f * hv2.y + 0.5f * s1;
            sK[lm * 516 + ln]     = s0;
            sK[lm * 516 + ln + 1] = s1;
        }
    }
    __syncthreads();

    // ---- phase 2: softmax per row; write attn (__stcs); keep tf32 P ----
    {
        float* aout = attn_out + ((size_t)bh * SS + q0) * SS;
        #pragma unroll 1
        for (int j = 0; j < 8; j++) {
            int r = warp * 8 + j;
            float* row = &sK[r * 516];
            float vals[16];
            float mx = -3e38f;
            #pragma unroll
            for (int i = 0; i < 16; i++) { vals[i] = row[lane + 32 * i]; mx = fmaxf(mx, vals[i]); }
            #pragma unroll
            for (int o = 16; o > 0; o >>= 1) mx = fmaxf(mx, __shfl_xor_sync(0xffffffffu, mx, o));
            float sum = 0.f;
            #pragma unroll
            for (int i = 0; i < 16; i++) { vals[i] = __expf(vals[i] - mx); sum += vals[i]; }
            #pragma unroll
            for (int o = 16; o > 0; o >>= 1) sum += __shfl_xor_sync(0xffffffffu, sum, o);
            float inv = 1.0f / sum;
            #pragma unroll
            for (int i = 0; i < 16; i++) {
                float p = vals[i] * inv;
                __stcs(&aout[(size_t)r * SS + lane + 32 * i], p);
                row[lane + 32 * i] = tf2f(p);
            }
        }
    }

    // ---- phase 3: ctx = P @ V, triple-buffered V chunks ----
    const int wm3 = warp & 3;
    const int wn3 = warp >> 2;
    float cacc[4][4];
    #pragma unroll
    for (int j = 0; j < 4; j++)
        #pragma unroll
        for (int k = 0; k < 4; k++) cacc[j][k] = 0.f;

    float* vbuf[3] = {vb0, vb1, vb2};
    #pragma unroll 1
    for (int ch = 0; ch < 8; ch++) {
        cp_wait<1>();
        __syncthreads();
        if (ch + 2 < 8) {
            float* dstb = vbuf[(ch + 3) % 3];
            const float* src = vsrcb + (size_t)(ch + 2) * 64 * DK;
            #pragma unroll
            for (int j = 0; j < 4; j++) {
                int idx = tid + 256 * j;
                int r = idx >> 4, c = (idx & 15) << 2;
                cp16(dstb + r * AST + c, src + r * DK + c);
            }
        }
        cp_commit();

        const float* sV = vbuf[(ch + 1) % 3];
        #pragma unroll 1
        for (int kk = 0; kk < 64; kk += 8) {
            unsigned a[4];
            int rb = wm3 * 16 + gid;
            int col = ch * 64 + kk + tig;
            a[0] = __float_as_uint(sK[rb * 516 + col]);
            a[1] = __float_as_uint(sK[(rb + 8) * 516 + col]);
            a[2] = __float_as_uint(sK[rb * 516 + col + 4]);
            a[3] = __float_as_uint(sK[(rb + 8) * 516 + col + 4]);
            #pragma unroll
            for (int nf = 0; nf < 4; nf++) {
                int nb = wn3 * 32 + nf * 8 + gid;
                unsigned bb0 = __float_as_uint(sV[(kk + tig) * AST + nb]);
                unsigned bb1 = __float_as_uint(sV[(kk + 4 + tig) * AST + nb]);
                mma8(cacc[nf], a, bb0, bb1);
            }
        }
    }

    #pragma unroll
    for (int rr = 0; rr < 2; rr++) {
        int s = q0 + wm3 * 16 + gid + rr * 8;
        #pragma unroll
        for (int nf = 0; nf < 4; nf++) {
            int d = wn3 * 32 + nf * 8 + tig * 2;
            *reinterpret_cast<float2*>(
                &g_ctx[((size_t)b * SS + s) * DD + h * DK + d]) =
                make_float2(tf2f(cacc[nf][rr * 2]), tf2f(cacc[nf][rr * 2 + 1]));
        }
    }
}

// =====================================================================
// LayerNorm over rows of g_res -> y output (block per row, float4)
// =====================================================================
__global__ __launch_bounds__(256)
void ln_kernel(const float* __restrict__ ln_g, const float* __restrict__ ln_b,
               float* __restrict__ y_out)
{
    __shared__ float rs[8], rq[8];
    const int r = blockIdx.x, t = threadIdx.x;
    const float4* row4 = reinterpret_cast<const float4*>(g_res + (size_t)r * DD);
    float4 v = row4[t];
    float s = v.x + v.y + v.z + v.w;
    float q = v.x * v.x + v.y * v.y + v.z * v.z + v.w * v.w;
    #pragma unroll
    for (int o = 16; o > 0; o >>= 1) {
        s += __shfl_xor_sync(0xffffffffu, s, o);
        q += __shfl_xor_sync(0xffffffffu, q, o);
    }
    if ((t & 31) == 0) { rs[t >> 5] = s; rq[t >> 5] = q; }
    __syncthreads();
    if (t < 32) {
        float ss = (t < 8) ? rs[t] : 0.f;
        float qq = (t < 8) ? rq[t] : 0.f;
        #pragma unroll
        for (int o = 4; o > 0; o >>= 1) {
            ss += __shfl_xor_sync(0xffffffffu, ss, o);
            qq += __shfl_xor_sync(0xffffffffu, qq, o);
        }
        if (t == 0) { rs[0] = ss; rq[0] = qq; }
    }
    __syncthreads();
    float mean = rs[0] * (1.0f / 1024.0f);
    float var  = rq[0] * (1.0f / 1024.0f) - mean * mean;
    float rstd = rsqrtf(var + 1e-5f);
    const float4 g4 = reinterpret_cast<const float4*>(ln_g)[t];
    const float4 b4 = reinterpret_cast<const float4*>(ln_b)[t];
    float4 o;
    o.x = (v.x - mean) * rstd * g4.x + b4.x;
    o.y = (v.y - mean) * rstd * g4.y + b4.y;
    o.z = (v.z - mean) * rstd * g4.z + b4.z;
    o.w = (v.w - mean) * rstd * g4.w + b4.w;
    reinterpret_cast<float4*>(y_out + (size_t)r * DD)[t] = o;
}

// =====================================================================
extern "C" void kernel_launch(void* const* d_in, const int* in_sizes, int n_in,
                              void* d_out, int out_size)
{
    const float* x    = (const float*)d_in[0];
    const float* Wq   = (const float*)d_in[1];
    const float* bq   = (const float*)d_in[2];
    const float* Wk   = (const float*)d_in[3];
    const float* bk   = (const float*)d_in[4];
    const float* Wv   = (const float*)d_in[5];
    const float* bv   = (const float*)d_in[6];
    const float* Wo   = (const float*)d_in[7];
    const float* bo   = (const float*)d_in[8];
    const float* ln_g = (const float*)d_in[9];
    const float* ln_b = (const float*)d_in[10];
    const float* hv   = (const float*)d_in[11];
    const int*   hm   = (const int*)d_in[12];
    const int*   am   = (const int*)d_in[13];

    float* out = (float*)d_out;
    float* y_out    = out;                          // [B,S,D]
    float* attn_out = out + (size_t)MTOT * DD;      // [B,H,S,S]

    cudaFuncSetAttribute(gemm_tf32_kernel<0>,
                         cudaFuncAttributeMaxDynamicSharedMemorySize, GEMM_SMEM_BYTES);
    cudaFuncSetAttribute(gemm_tf32_kernel<1>,
                         cudaFuncAttributeMaxDynamicSharedMemorySize, GEMM_SMEM_BYTES);
    cudaFuncSetAttribute(attn_fused_kernel,
                         cudaFuncAttributeMaxDynamicSharedMemorySize, ATTN_SMEM_BYTES);

    // 0) prep: round x; round+transpose weights -> [N][K]
    prep_round_x<<<dim3(148), 256>>>(x);
    prep_transpose_w<<<dim3(32, 32, 4), 256>>>(Wq, Wk, Wv, Wo);
    // 1) QKV projections
    gemm_tf32_kernel<0><<<dim3(32, 8, 3), 256, GEMM_SMEM_BYTES>>>(bq, bk, bv, nullptr);
    // 2) fused attention
    attn_fused_kernel<<<dim3(BHTOT, 8), 256, ATTN_SMEM_BYTES>>>(hv, hm, am, attn_out);
    // 3) out projection + bias + residual
    gemm_tf32_kernel<1><<<dim3(32, 8, 1), 256, GEMM_SMEM_BYTES>>>(bo, bo, bo, x);
    // 4) LayerNorm -> y
    ln_kernel<<<dim3(MTOT), 256>>>(ln_g, ln_b, y_out);
}

// round 12
// speedup vs baseline: 1.7939x; 1.1047x over previous
#include <cuda_runtime.h>
#include <cstdint>

#define NEG_INF_F (-1e9f)
#define HTHRESH_F (-1e8f)

// B=8, S=512, D=1024, H=16, DK=64
#define BB 8
#define SS 512
#define DD 1024
#define HH 16
#define DK 64
#define MTOT (BB*SS)          // 4096
#define BHTOT (BB*HH)         // 128

// -------- scratch (device globals; no cudaMalloc allowed) --------
__device__ float g_q[BB*HH*SS*DK];
__device__ float g_k[BB*HH*SS*DK];
__device__ float g_v[BB*HH*SS*DK];
__device__ float g_ctx[MTOT*DD];
__device__ float g_res[MTOT*DD];
__device__ float g_xr[MTOT*DD];     // tf32-rounded x
// tf32-rounded, TRANSPOSED weights [N][K] (n-major rows for ldmatrix B-frags)
__device__ float g_wqt[DD*DD];
__device__ float g_wkt[DD*DD];
__device__ float g_wvt[DD*DD];
__device__ float g_wot[DD*DD];
// bit-packed masks: 512 cols -> 16 uint32 words per row
__device__ unsigned g_hmp[BHTOT*SS*16];   // 4 MB
__device__ unsigned g_amp[BB*SS*16];      // 256 KB

// -------- helpers --------
__device__ __forceinline__ unsigned f2tf(float f) {
    unsigned u;
    asm("cvt.rna.tf32.f32 %0, %1;" : "=r"(u) : "f"(f));
    return u;
}
__device__ __forceinline__ float tf2f(float f) {
    return __uint_as_float(f2tf(f));
}
__device__ __forceinline__ void mma8(float c[4], const unsigned a[4], unsigned b0, unsigned b1) {
    asm volatile(
        "mma.sync.aligned.m16n8k8.row.col.f32.tf32.tf32.f32 "
        "{%0,%1,%2,%3}, {%4,%5,%6,%7}, {%8,%9}, {%0,%1,%2,%3};\n"
        : "+f"(c[0]), "+f"(c[1]), "+f"(c[2]), "+f"(c[3])
        : "r"(a[0]), "r"(a[1]), "r"(a[2]), "r"(a[3]), "r"(b0), "r"(b1));
}
// ldmatrix.x4 on 32-bit data: submatrix s = 8 rows x 4 dwords; lanes 8s..8s+7
// supply row addresses; output reg s: lane j holds (row j/4, dword j%4).
__device__ __forceinline__ void ldsm4(unsigned r[4], unsigned saddr) {
    asm volatile("ldmatrix.sync.aligned.m8n8.x4.shared.b16 {%0,%1,%2,%3}, [%4];\n"
                 : "=r"(r[0]), "=r"(r[1]), "=r"(r[2]), "=r"(r[3]) : "r"(saddr));
}
__device__ __forceinline__ void cp16(float* smem_dst, const float* gsrc) {
    unsigned d = (unsigned)__cvta_generic_to_shared(smem_dst);
    asm volatile("cp.async.cg.shared.global [%0], [%1], 16;\n" :: "r"(d), "l"(gsrc));
}
__device__ __forceinline__ void cp_commit() {
    asm volatile("cp.async.commit_group;\n");
}
template<int N>
__device__ __forceinline__ void cp_wait() {
    asm volatile("cp.async.wait_group %0;\n" :: "n"(N));
}

// =====================================================================
// Prep kernels
// =====================================================================
__global__ __launch_bounds__(256)
void prep_round_x(const float* __restrict__ x)
{
    float4* dst = (float4*)g_xr;
    const float4* src = (const float4*)x;
    const int n4 = MTOT * DD / 4;
    for (int i = blockIdx.x * blockDim.x + threadIdx.x; i < n4;
         i += gridDim.x * blockDim.x) {
        float4 v = src[i];
        v.x = tf2f(v.x); v.y = tf2f(v.y); v.z = tf2f(v.z); v.w = tf2f(v.w);
        dst[i] = v;
    }
}
__global__ __launch_bounds__(256)
void prep_transpose_w(const float* __restrict__ Wq, const float* __restrict__ Wk,
                      const float* __restrict__ Wv, const float* __restrict__ Wo)
{
    __shared__ float t[32][33];
    const int z = blockIdx.z;
    const float* W = (z == 0) ? Wq : (z == 1 ? Wk : (z == 2 ? Wv : Wo));
    float* WT = (z == 0) ? g_wqt : (z == 1 ? g_wkt : (z == 2 ? g_wvt : g_wot));
    const int k0 = blockIdx.x * 32;
    const int n0 = blockIdx.y * 32;
    const int tx = threadIdx.x & 31, ty = threadIdx.x >> 5;
    #pragma unroll
    for (int j = 0; j < 4; j++) {
        int k = k0 + ty + j * 8;
        t[ty + j * 8][tx] = tf2f(W[(size_t)k * DD + n0 + tx]);
    }
    __syncthreads();
    #pragma unroll
    for (int j = 0; j < 4; j++) {
        int n = n0 + ty + j * 8;
        WT[(size_t)n * DD + k0 + tx] = t[tx][ty + j * 8];
    }
}
// Pack 0/1 int32 masks into bitmasks: one warp per 512-col row.
__global__ __launch_bounds__(256)
void pack_masks(const int* __restrict__ hm, const int* __restrict__ am)
{
    const int warp = threadIdx.x >> 5, lane = threadIdx.x & 31;
    const int row = blockIdx.x * 8 + warp;
    if (blockIdx.y == 0) {
        const int* src = hm + (size_t)row * SS;
        unsigned* dst = g_hmp + (size_t)row * 16;
        #pragma unroll
        for (int i = 0; i < 16; i++) {
            unsigned w = __ballot_sync(0xffffffffu, src[i * 32 + lane] != 0);
            if (lane == 0) dst[i] = w;
        }
    } else {
        if (row >= BB * SS) return;
        const int* src = am + (size_t)row * SS;
        unsigned* dst = g_amp + (size_t)row * 16;
        #pragma unroll
        for (int i = 0; i < 16; i++) {
            unsigned w = __ballot_sync(0xffffffffu, src[i * 32 + lane] != 0);
            if (lane == 0) dst[i] = w;
        }
    }
}

// =====================================================================
// GEMM: C[4096,1024] = A @ W (+bias [+residual])
// 128x128x32 tiles, 3-stage cp.async pipeline, XOR-swizzled smem.
// A-frags AND B-frags via ldmatrix.x4 (B stored n-major from W^T).
// =====================================================================
#define GBM 128
#define GBN 128
#define GBK 32
#define GST 3
#define TILE_F (GBM * GBK)
#define GEMM_SMEM_BYTES (GST * TILE_F * 2 * 4)   // 98304

template<int MODE>
__global__ __launch_bounds__(256, 2)
void gemm_tf32_kernel(const float* __restrict__ bias0, const float* __restrict__ bias1,
                      const float* __restrict__ bias2,
                      const float* __restrict__ xres)
{
    extern __shared__ float gsm[];
    float* sA = gsm;
    float* sB = gsm + GST * TILE_F;

    const int z = blockIdx.z;
    const float* WT   = (MODE == 1) ? g_wot : ((z == 0) ? g_wqt : (z == 1 ? g_wkt : g_wvt));
    const float* bias = (z == 0) ? bias0 : (z == 1 ? bias1 : bias2);
    const float* A    = (MODE == 0) ? g_xr : g_ctx;
    float* dst = (MODE == 0) ? ((z == 0) ? g_q : (z == 1 ? g_k : g_v)) : g_res;

    const int m0 = blockIdx.x * GBM;
    const int n0 = blockIdx.y * GBN;
    const int tid = threadIdx.x;
    const int warp = tid >> 5, lane = tid & 31, gid = lane >> 2, tig = lane & 3;
    const int wm = warp & 1, wn = warp >> 1;

    const int l7  = lane & 7;
    const int lhA = (lane >> 3) & 1;
    const int khA = lane >> 4;
    const int khB = (lane >> 3) & 1;
    const int nsB = lane >> 4;

    float acc[4][4][4];
    #pragma unroll
    for (int i = 0; i < 4; i++)
        #pragma unroll
        for (int j = 0; j < 4; j++)
            #pragma unroll
            for (int k = 0; k < 4; k++) acc[i][j][k] = 0.f;

    auto load_tile = [&](int st, int kt) {
        float* dA = sA + st * TILE_F;
        float* dB = sB + st * TILE_F;
        #pragma unroll
        for (int j = 0; j < 4; j++) {
            int idx = tid + 256 * j;
            int r = idx >> 3, c = idx & 7;
            cp16(dA + r * 32 + ((c ^ (r & 7)) << 2),
                 A + (size_t)(m0 + r) * DD + kt + (c << 2));
        }
        #pragma unroll
        for (int j = 0; j < 4; j++) {
            int idx = tid + 256 * j;
            int r = idx >> 3, c = idx & 7;
            cp16(dB + r * 32 + ((c ^ (r & 7)) << 2),
                 WT + (size_t)(n0 + r) * DD + kt + (c << 2));
        }
    };

    #pragma unroll
    for (int s = 0; s < GST - 1; s++) { load_tile(s, s * GBK); cp_commit(); }

    const int NIT = DD / GBK;
    for (int it = 0; it < NIT; it++) {
        cp_wait<GST - 2>();
        __syncthreads();
        int nxt = it + GST - 1;
        if (nxt < NIT) load_tile(nxt % GST, nxt * GBK);
        cp_commit();

        const unsigned tAs = (unsigned)__cvta_generic_to_shared(sA + (it % GST) * TILE_F);
        const unsigned tBs = (unsigned)__cvta_generic_to_shared(sB + (it % GST) * TILE_F);
        #pragma unroll
        for (int kk = 0; kk < GBK; kk += 8) {
            const int c0 = kk >> 2;
            unsigned a[4][4];
            #pragma unroll
            for (int mf = 0; mf < 4; mf++) {
                int row = wm * 64 + mf * 16 + lhA * 8 + l7;
                unsigned saddr = tAs + ((row * 32 + (((c0 + khA) ^ l7) << 2)) << 2);
                ldsm4(a[mf], saddr);
            }
            unsigned b[2][4];
            #pragma unroll
            for (int p = 0; p < 2; p++) {
                int row = wn * 32 + p * 16 + nsB * 8 + l7;
                unsigned saddr = tBs + ((row * 32 + (((c0 + khB) ^ l7) << 2)) << 2);
                ldsm4(b[p], saddr);
            }
            #pragma unroll
            for (int p = 0; p < 2; p++)
                #pragma unroll
                for (int h = 0; h < 2; h++) {
                    const int nf = p * 2 + h;
                    #pragma unroll
                    for (int mf = 0; mf < 4; mf++)
                        mma8(acc[mf][nf], a[mf], b[p][2 * h], b[p][2 * h + 1]);
                }
        }
    }

    #pragma unroll
    for (int mf = 0; mf < 4; mf++) {
        #pragma unroll
        for (int rr = 0; rr < 2; rr++) {
            int m = m0 + wm * 64 + mf * 16 + gid + rr * 8;
            #pragma unroll
            for (int nf = 0; nf < 4; nf++) {
                int n = n0 + wn * 32 + nf * 8 + tig * 2;
                float v0 = acc[mf][nf][rr * 2 + 0] + bias[n];
                float v1 = acc[mf][nf][rr * 2 + 1] + bias[n + 1];
                if (MODE == 0) {
                    int bidx = m >> 9, s = m & 511, hh = n >> 6, d = n & 63;
                    *reinterpret_cast<float2*>(
                        &dst[(((size_t)bidx * HH + hh) * SS + s) * DK + d]) =
                        make_float2(tf2f(v0), tf2f(v1));
                } else {
                    v0 += xres[(size_t)m * DD + n];
                    v1 += xres[(size_t)m * DD + n + 1];
                    *reinterpret_cast<float2*>(&dst[(size_t)m * DD + n]) = make_float2(v0, v1);
                }
            }
        }
    }
}

// =====================================================================
// Fused attention kernel: block = (b,h, 64-row q-tile), 256 threads.
//   masks arrive bit-packed (8KB smem, cp.async'd with Q/K)
//   blend: hv-only PF=4 __ldcs ring, pre-issued before phase 1
// =====================================================================
#define AST 72
#define SK_FLOATS (512 * AST)
#define VB_FLOATS (64 * AST)
#define MASK_WORDS (64 * 16)               // per mask: 1024 words = 4KB
#define ATTN_SMEM_BYTES ((SK_FLOATS + 3 * VB_FLOATS + 2 * MASK_WORDS) * 4)  // 210944
#define PF 4

__global__ __launch_bounds__(256)
void attn_fused_kernel(const float* __restrict__ help_vals,
                       float* __restrict__ attn_out)
{
    extern __shared__ float smem[];
    float* sK = smem;
    float* vb0 = smem + SK_FLOATS;
    float* vb1 = vb0 + VB_FLOATS;
    float* vb2 = vb1 + VB_FLOATS;
    unsigned* sMH = (unsigned*)(vb2 + VB_FLOATS);
    unsigned* sMA = sMH + MASK_WORDS;

    const int bh = blockIdx.x;
    const int b = bh >> 4;
    const int h = bh & 15;
    const int q0 = blockIdx.y * 64;
    const int tid = threadIdx.x;
    const int warp = tid >> 5, lane = tid & 31, gid = lane >> 2, tig = lane & 3;

    const float* vsrcb = g_v + (size_t)bh * SS * DK;

    // ---- async load Q tile, full K, and bit-packed masks ----
    {
        const float* qsrc = g_q + ((size_t)bh * SS + q0) * DK;
        #pragma unroll
        for (int j = 0; j < 4; j++) {
            int idx = tid + 256 * j;
            int r = idx >> 4, c = (idx & 15) << 2;
            cp16(vb0 + r * AST + c, qsrc + r * DK + c);
        }
        const float* ksrc = g_k + (size_t)bh * SS * DK;
        #pragma unroll
        for (int j = 0; j < 32; j++) {
            int idx = tid + 256 * j;
            int r = idx >> 4, c = (idx & 15) << 2;
            cp16(sK + r * AST + c, ksrc + r * DK + c);
        }
        {   // masks: 64 rows x 16 words each; 4 cp16 per row
            int r = tid >> 2, c = (tid & 3) << 2;
            cp16((float*)(sMH + r * 16 + c),
                 (const float*)(g_hmp + ((size_t)bh * SS + q0 + r) * 16 + c));
            cp16((float*)(sMA + r * 16 + c),
                 (const float*)(g_amp + ((size_t)b * SS + q0 + r) * 16 + c));
        }
        cp_commit();
        cp_wait<0>();
        __syncthreads();
    }

    const int wm = warp & 1;
    const int wn = warp >> 1;

    // ---- pre-issue first hv batch (overlaps phase-1 mma) ----
    const float* hvp = help_vals + ((size_t)bh * SS + q0) * SS;
    const int base_lm = wm * 32 + gid;
    const int base_ln = wn * 128 + tig * 2;

    float2 hvb[PF];
    #pragma unroll
    for (int i = 0; i < PF; i++) {
        int lm = base_lm + ((i >> 5) << 4) + (((i >> 4) & 1) << 3);
        int ln = base_ln + ((i & 15) << 3);
        hvb[i] = __ldcs(reinterpret_cast<const float2*>(hvp + (size_t)lm * SS + ln));
    }

    // ---- phase 1: scores = Q @ K^T ----
    float acc[2][16][4];
    #pragma unroll
    for (int i = 0; i < 2; i++)
        #pragma unroll
        for (int j = 0; j < 16; j++)
            #pragma unroll
            for (int k = 0; k < 4; k++) acc[i][j][k] = 0.f;

    #pragma unroll 1
    for (int kk = 0; kk < DK; kk += 8) {
        unsigned a[2][4];
        #pragma unroll
        for (int mf = 0; mf < 2; mf++) {
            int rb = wm * 32 + mf * 16 + gid;
            a[mf][0] = __float_as_uint(vb0[rb * AST + kk + tig]);
            a[mf][1] = __float_as_uint(vb0[(rb + 8) * AST + kk + tig]);
            a[mf][2] = __float_as_uint(vb0[rb * AST + kk + 4 + tig]);
            a[mf][3] = __float_as_uint(vb0[(rb + 8) * AST + kk + 4 + tig]);
        }
        #pragma unroll
        for (int nf = 0; nf < 16; nf++) {
            int nb = wn * 128 + nf * 8 + gid;
            unsigned bb0 = __float_as_uint(sK[nb * AST + kk + tig]);
            unsigned bb1 = __float_as_uint(sK[nb * AST + kk + 4 + tig]);
            mma8(acc[0][nf], a[0], bb0, bb1);
            mma8(acc[1][nf], a[1], bb0, bb1);
        }
    }
    __syncthreads();   // K/Q dead; overlay scores on sK

    // prefetch V chunks 0,1 (land during blend + softmax)
    {
        #pragma unroll
        for (int j = 0; j < 4; j++) {
            int idx = tid + 256 * j;
            int r = idx >> 4, c = (idx & 15) << 2;
            cp16(vb1 + r * AST + c, vsrcb + r * DK + c);
        }
        cp_commit();
        #pragma unroll
        for (int j = 0; j < 4; j++) {
            int idx = tid + 256 * j;
            int r = idx >> 4, c = (idx & 15) << 2;
            cp16(vb2 + r * AST + c, vsrcb + (64 + r) * DK + c);
        }
        cp_commit();
    }

    // ---- blend: scale + attn_mask + dependency blend -> sK ----
    {
        #pragma unroll
        for (int i = 0; i < 64; i++) {
            const int slot = i & (PF - 1);
            float2 hv2 = hvb[slot];
            if (i + PF < 64) {
                int j = i + PF;
                int lmp = base_lm + ((j >> 5) << 4) + (((j >> 4) & 1) << 3);
                int lnp = base_ln + ((j & 15) << 3);
                hvb[slot] = __ldcs(reinterpret_cast<const float2*>(
                    hvp + (size_t)lmp * SS + lnp));
            }
            const int mf = i >> 5, rr = (i >> 4) & 1, nf = i & 15;
            const int lm = base_lm + (mf << 4) + (rr << 3);
            const int ln = base_ln + (nf << 3);
            const unsigned wh = sMH[lm * 16 + (ln >> 5)];
            const unsigned wa = sMA[lm * 16 + (ln >> 5)];
            const int sh = ln & 31;
            float s0 = ((wa >> sh) & 1u) ? NEG_INF_F : acc[mf][nf][rr * 2 + 0] * 0.125f;
            float s1 = ((wa >> (sh + 1)) & 1u) ? NEG_INF_F : acc[mf][nf][rr * 2 + 1] * 0.125f;
            if (((wh >> sh) & 1u) && hv2.x > HTHRESH_F) s0 = 0.5f * hv2.x + 0.5f * s0;
            if (((wh >> (sh + 1)) & 1u) && hv2.y > HTHRESH_F) s1 = 0.5f * hv2.y + 0.5f * s1;
            sK[lm * 516 + ln]     = s0;
            sK[lm * 516 + ln + 1] = s1;
        }
    }
    __syncthreads();

    // ---- phase 2: softmax per row; write attn (__stcs); keep tf32 P ----
    {
        float* aout = attn_out + ((size_t)bh * SS + q0) * SS;
        #pragma unroll 1
        for (int j = 0; j < 8; j++) {
            int r = warp * 8 + j;
            float* row = &sK[r * 516];
            float vals[16];
            float mx = -3e38f;
            #pragma unroll
            for (int i = 0; i < 16; i++) { vals[i] = row[lane + 32 * i]; mx = fmaxf(mx, vals[i]); }
            #pragma unroll
            for (int o = 16; o > 0; o >>= 1) mx = fmaxf(mx, __shfl_xor_sync(0xffffffffu, mx, o));
            float sum = 0.f;
            #pragma unroll
            for (int i = 0; i < 16; i++) { vals[i] = __expf(vals[i] - mx); sum += vals[i]; }
            #pragma unroll
            for (int o = 16; o > 0; o >>= 1) sum += __shfl_xor_sync(0xffffffffu, sum, o);
            float inv = 1.0f / sum;
            #pragma unroll
            for (int i = 0; i < 16; i++) {
                float p = vals[i] * inv;
                __stcs(&aout[(size_t)r * SS + lane + 32 * i], p);
                row[lane + 32 * i] = tf2f(p);
            }
        }
    }

    // ---- phase 3: ctx = P @ V, triple-buffered V chunks ----
    const int wm3 = warp & 3;
    const int wn3 = warp >> 2;
    float cacc[4][4];
    #pragma unroll
    for (int j = 0; j < 4; j++)
        #pragma unroll
        for (int k = 0; k < 4; k++) cacc[j][k] = 0.f;

    float* vbuf[3] = {vb0, vb1, vb2};
    #pragma unroll 1
    for (int ch = 0; ch < 8; ch++) {
        cp_wait<1>();
        __syncthreads();
        if (ch + 2 < 8) {
            float* dstb = vbuf[(ch + 3) % 3];
            const float* src = vsrcb + (size_t)(ch + 2) * 64 * DK;
            #pragma unroll
            for (int j = 0; j < 4; j++) {
                int idx = tid + 256 * j;
                int r = idx >> 4, c = (idx & 15) << 2;
                cp16(dstb + r * AST + c, src + r * DK + c);
            }
        }
        cp_commit();

        const float* sV = vbuf[(ch + 1) % 3];
        #pragma unroll 1
        for (int kk = 0; kk < 64; kk += 8) {
            unsigned a[4];
            int rb = wm3 * 16 + gid;
            int col = ch * 64 + kk + tig;
            a[0] = __float_as_uint(sK[rb * 516 + col]);
            a[1] = __float_as_uint(sK[(rb + 8) * 516 + col]);
            a[2] = __float_as_uint(sK[rb * 516 + col + 4]);
            a[3] = __float_as_uint(sK[(rb + 8) * 516 + col + 4]);
            #pragma unroll
            for (int nf = 0; nf < 4; nf++) {
                int nb = wn3 * 32 + nf * 8 + gid;
                unsigned bb0 = __float_as_uint(sV[(kk + tig) * AST + nb]);
                unsigned bb1 = __float_as_uint(sV[(kk + 4 + tig) * AST + nb]);
                mma8(cacc[nf], a, bb0, bb1);
            }
        }
    }

    #pragma unroll
    for (int rr = 0; rr < 2; rr++) {
        int s = q0 + wm3 * 16 + gid + rr * 8;
        #pragma unroll
        for (int nf = 0; nf < 4; nf++) {
            int d = wn3 * 32 + nf * 8 + tig * 2;
            *reinterpret_cast<float2*>(
                &g_ctx[((size_t)b * SS + s) * DD + h * DK + d]) =
                make_float2(tf2f(cacc[nf][rr * 2]), tf2f(cacc[nf][rr * 2 + 1]));
        }
    }
}

// =====================================================================
// LayerNorm over rows of g_res -> y output (block per row, float4)
// =====================================================================
__global__ __launch_bounds__(256)
void ln_kernel(const float* __restrict__ ln_g, const float* __restrict__ ln_b,
               float* __restrict__ y_out)
{
    __shared__ float rs[8], rq[8];
    const int r = blockIdx.x, t = threadIdx.x;
    const float4* row4 = reinterpret_cast<const float4*>(g_res + (size_t)r * DD);
    float4 v = row4[t];
    float s = v.x + v.y + v.z + v.w;
    float q = v.x * v.x + v.y * v.y + v.z * v.z + v.w * v.w;
    #pragma unroll
    for (int o = 16; o > 0; o >>= 1) {
        s += __shfl_xor_sync(0xffffffffu, s, o);
        q += __shfl_xor_sync(0xffffffffu, q, o);
    }
    if ((t & 31) == 0) { rs[t >> 5] = s; rq[t >> 5] = q; }
    __syncthreads();
    if (t < 32) {
        float ss = (t < 8) ? rs[t] : 0.f;
        float qq = (t < 8) ? rq[t] : 0.f;
        #pragma unroll
        for (int o = 4; o > 0; o >>= 1) {
            ss += __shfl_xor_sync(0xffffffffu, ss, o);
            qq += __shfl_xor_sync(0xffffffffu, qq, o);
        }
        if (t == 0) { rs[0] = ss; rq[0] = qq; }
    }
    __syncthreads();
    float mean = rs[0] * (1.0f / 1024.0f);
    float var  = rq[0] * (1.0f / 1024.0f) - mean * mean;
    float rstd = rsqrtf(var + 1e-5f);
    const float4 g4 = reinterpret_cast<const float4*>(ln_g)[t];
    const float4 b4 = reinterpret_cast<const float4*>(ln_b)[t];
    float4 o;
    o.x = (v.x - mean) * rstd * g4.x + b4.x;
    o.y = (v.y - mean) * rstd * g4.y + b4.y;
    o.z = (v.z - mean) * rstd * g4.z + b4.z;
    o.w = (v.w - mean) * rstd * g4.w + b4.w;
    reinterpret_cast<float4*>(y_out + (size_t)r * DD)[t] = o;
}

// =====================================================================
extern "C" void kernel_launch(void* const* d_in, const int* in_sizes, int n_in,
                              void* d_out, int out_size)
{
    const float* x    = (const float*)d_in[0];
    const float* Wq   = (const float*)d_in[1];
    const float* bq   = (const float*)d_in[2];
    const float* Wk   = (const float*)d_in[3];
    const float* bk   = (const float*)d_in[4];
    const float* Wv   = (const float*)d_in[5];
    const float* bv   = (const float*)d_in[6];
    const float* Wo   = (const float*)d_in[7];
    const float* bo   = (const float*)d_in[8];
    const float* ln_g = (const float*)d_in[9];
    const float* ln_b = (const float*)d_in[10];
    const float* hv   = (const float*)d_in[11];
    const int*   hm   = (const int*)d_in[12];
    const int*   am   = (const int*)d_in[13];

    float* out = (float*)d_out;
    float* y_out    = out;                          // [B,S,D]
    float* attn_out = out + (size_t)MTOT * DD;      // [B,H,S,S]

    cudaFuncSetAttribute(gemm_tf32_kernel<0>,
                         cudaFuncAttributeMaxDynamicSharedMemorySize, GEMM_SMEM_BYTES);
    cudaFuncSetAttribute(gemm_tf32_kernel<1>,
                         cudaFuncAttributeMaxDynamicSharedMemorySize, GEMM_SMEM_BYTES);
    cudaFuncSetAttribute(attn_fused_kernel,
                         cudaFuncAttributeMaxDynamicSharedMemorySize, ATTN_SMEM_BYTES);

    // 0) prep: round x; round+transpose weights; pack masks to bits
    prep_round_x<<<dim3(148), 256>>>(x);
    prep_transpose_w<<<dim3(32, 32, 4), 256>>>(Wq, Wk, Wv, Wo);
    pack_masks<<<dim3(8192, 2), 256>>>(hm, am);
    // 1) QKV projections
    gemm_tf32_kernel<0><<<dim3(32, 8, 3), 256, GEMM_SMEM_BYTES>>>(bq, bk, bv, nullptr);
    // 2) fused attention
    attn_fused_kernel<<<dim3(BHTOT, 8), 256, ATTN_SMEM_BYTES>>>(hv, attn_out);
    // 3) out projection + bias + residual
    gemm_tf32_kernel<1><<<dim3(32, 8, 1), 256, GEMM_SMEM_BYTES>>>(bo, bo, bo, x);
    // 4) LayerNorm -> y
    ln_kernel<<<dim3(MTOT), 256>>>(ln_g, ln_b, y_out);
}